// round 1
// baseline (speedup 1.0000x reference)
#include <cuda_runtime.h>
#include <math.h>

// ---------------- problem constants ----------------
#define BB 8
#define NN 8192
#define CC 512
#define KK 64
#define DD 128
#define TOKN 256
#define MTOT (BB*NN)          // 65536
#define HDIM 1024             // concat hidden (c: 0..511, s: 512..1023)
#define OUTW (TOKN + DD*KK)   // 8448

// ---------------- scratch (device globals; no cudaMalloc allowed) ----------------
__device__ float g_H[(size_t)MTOT * HDIM];          // layer-1 activations (268 MB)
__device__ float g_S[(size_t)BB * 65 * NN];         // augmented score matrix [b,65,n]
__device__ float g_P[(size_t)BB * KK * NN];         // matching probs
__device__ float g_local[(size_t)MTOT * DD];        // local features
__device__ float g_u[BB * 65];
__device__ float g_v[BB * NN];
__device__ float g_gp[BB * 32 * CC];                // GeM partials
__device__ float g_g[BB * CC];                      // GeM pooled
__device__ float g_gt[BB * TOKN];                   // global token
__device__ float g_aggp[(size_t)BB * 32 * DD * KK]; // agg split-K partials
__device__ float g_agg[BB * DD * KK];

__device__ __forceinline__ float compute_p(float w) {
    float sp = (w > 20.f) ? w : log1pf(expf(w));
    return fminf(sp + 1e-3f, 10.0f);
}

// ---------------- init ----------------
__global__ void k_zero_v() {
    int i = blockIdx.x * 256 + threadIdx.x;  // 65536
    g_v[i] = 0.f;
}

// ---------------- GeM pooling ----------------
__global__ void k_gem_part(const float* __restrict__ x, const float* __restrict__ gem_w) {
    int b = blockIdx.y, part = blockIdx.x, c = threadIdx.x;  // 512 threads
    float p = compute_p(gem_w[0]);
    bool cube = fabsf(p - 3.0f) < 1e-5f;
    const float* xp = x + ((size_t)b * NN + part * 256) * CC + c;
    float s = 0.f;
    if (cube) {
        #pragma unroll 4
        for (int n = 0; n < 256; n++) {
            float v = fmaxf(xp[(size_t)n * CC], 1e-6f);
            s += v * v * v;
        }
    } else {
        for (int n = 0; n < 256; n++) {
            float v = fmaxf(xp[(size_t)n * CC], 1e-6f);
            s += __powf(v, p);
        }
    }
    g_gp[(b * 32 + part) * CC + c] = s;
}

__global__ void k_gem_fin(const float* __restrict__ gem_w) {
    int b = blockIdx.x, c = threadIdx.x;
    float s = 0.f;
    #pragma unroll
    for (int i = 0; i < 32; i++) s += g_gp[(b * 32 + i) * CC + c];
    float p = compute_p(gem_w[0]);
    float mean = s * (1.0f / (float)NN);
    float g = powf(mean, 1.0f / p);
    if (!isfinite(g)) g = 0.f;
    g_g[b * CC + c] = g;
}

// ---------------- token MLP (tiny) ----------------
__global__ void k_tok(const float* __restrict__ tW1, const float* __restrict__ tb1,
                      const float* __restrict__ tW2, const float* __restrict__ tb2) {
    int b = blockIdx.x, t = threadIdx.x;  // 512 threads
    __shared__ float gs[512], hs[512];
    gs[t] = g_g[b * CC + t];
    __syncthreads();
    float acc = tb1[t];
    const float* w = tW1 + (size_t)t * CC;
    #pragma unroll 8
    for (int c = 0; c < CC; c++) acc = fmaf(gs[c], w[c], acc);
    hs[t] = fmaxf(acc, 0.f);
    __syncthreads();
    if (t < TOKN) {
        float a2 = tb2[t];
        const float* w2 = tW2 + (size_t)t * 512;
        #pragma unroll 8
        for (int j = 0; j < 512; j++) a2 = fmaf(hs[j], w2[j], a2);
        g_gt[b * TOKN + t] = a2;
    }
}

// ---------------- layer-1 GEMM: H = relu(X @ [cW1;sW1]^T + b) ----------------
// grid (8, 512), block 256; BM=128 BN=128 BK=16, 8x8 microtile
__global__ __launch_bounds__(256) void k_gemm1(const float* __restrict__ X,
                                               const float* __restrict__ Wc, const float* __restrict__ bc,
                                               const float* __restrict__ Ws, const float* __restrict__ bs) {
    __shared__ float As[16][128];
    __shared__ float Bs[16][128];
    int tid = threadIdx.x;
    int m0 = blockIdx.y * 128;
    int col0 = blockIdx.x * 128;
    const float* W    = (col0 < 512) ? (Wc + (size_t)col0 * CC) : (Ws + (size_t)(col0 - 512) * CC);
    const float* bias = (col0 < 512) ? (bc + col0) : (bs + (col0 - 512));
    float acc[8][8];
    #pragma unroll
    for (int i = 0; i < 8; i++)
        #pragma unroll
        for (int j = 0; j < 8; j++) acc[i][j] = 0.f;
    int tx = tid & 15, ty = tid >> 4;

    for (int kb = 0; kb < CC; kb += 16) {
        #pragma unroll
        for (int t = 0; t < 2; t++) {
            int v = tid * 2 + t;             // 0..511
            int row = v >> 2, kq = (v & 3) * 4;
            float4 a = *reinterpret_cast<const float4*>(X + (size_t)(m0 + row) * CC + kb + kq);
            As[kq + 0][row] = a.x; As[kq + 1][row] = a.y; As[kq + 2][row] = a.z; As[kq + 3][row] = a.w;
            float4 bv = *reinterpret_cast<const float4*>(W + (size_t)row * CC + kb + kq);
            Bs[kq + 0][row] = bv.x; Bs[kq + 1][row] = bv.y; Bs[kq + 2][row] = bv.z; Bs[kq + 3][row] = bv.w;
        }
        __syncthreads();
        #pragma unroll
        for (int k = 0; k < 16; k++) {
            float a[8], bb[8];
            #pragma unroll
            for (int i = 0; i < 8; i++) a[i] = As[k][ty * 8 + i];
            #pragma unroll
            for (int j = 0; j < 8; j++) bb[j] = Bs[k][tx * 8 + j];
            #pragma unroll
            for (int i = 0; i < 8; i++)
                #pragma unroll
                for (int j = 0; j < 8; j++) acc[i][j] = fmaf(a[i], bb[j], acc[i][j]);
        }
        __syncthreads();
    }
    #pragma unroll
    for (int i = 0; i < 8; i++) {
        size_t base = (size_t)(m0 + ty * 8 + i) * HDIM + col0 + tx * 8;
        #pragma unroll
        for (int j = 0; j < 8; j++)
            g_H[base + j] = fmaxf(acc[i][j] + bias[tx * 8 + j], 0.f);
    }
}

// ---------------- layer-2 GEMM (BN=64): local (mode 0) / scores->S^T (mode 1) ----------------
__global__ __launch_bounds__(256) void k_gemm2(int aoff,
                                               const float* __restrict__ W, const float* __restrict__ bias,
                                               int outMode) {
    __shared__ float As[16][128];
    __shared__ float Bs[16][64];
    int tid = threadIdx.x;
    int m0 = blockIdx.y * 128;
    int col0 = blockIdx.x * 64;
    float acc[8][4];
    #pragma unroll
    for (int i = 0; i < 8; i++)
        #pragma unroll
        for (int j = 0; j < 4; j++) acc[i][j] = 0.f;
    int tx = tid & 15, ty = tid >> 4;

    for (int kb = 0; kb < CC; kb += 16) {
        #pragma unroll
        for (int t = 0; t < 2; t++) {
            int v = tid * 2 + t;
            int row = v >> 2, kq = (v & 3) * 4;
            float4 a = *reinterpret_cast<const float4*>(&g_H[(size_t)(m0 + row) * HDIM + aoff + kb + kq]);
            As[kq + 0][row] = a.x; As[kq + 1][row] = a.y; As[kq + 2][row] = a.z; As[kq + 3][row] = a.w;
        }
        {
            int v = tid;                     // 0..255
            int n = v >> 2, kq = (v & 3) * 4;
            float4 bv = *reinterpret_cast<const float4*>(W + (size_t)(col0 + n) * CC + kb + kq);
            Bs[kq + 0][n] = bv.x; Bs[kq + 1][n] = bv.y; Bs[kq + 2][n] = bv.z; Bs[kq + 3][n] = bv.w;
        }
        __syncthreads();
        #pragma unroll
        for (int k = 0; k < 16; k++) {
            float a[8], bb[4];
            #pragma unroll
            for (int i = 0; i < 8; i++) a[i] = As[k][ty * 8 + i];
            #pragma unroll
            for (int j = 0; j < 4; j++) bb[j] = Bs[k][tx * 4 + j];
            #pragma unroll
            for (int i = 0; i < 8; i++)
                #pragma unroll
                for (int j = 0; j < 4; j++) acc[i][j] = fmaf(a[i], bb[j], acc[i][j]);
        }
        __syncthreads();
    }
    if (outMode == 0) {
        #pragma unroll
        for (int i = 0; i < 8; i++) {
            size_t base = (size_t)(m0 + ty * 8 + i) * DD + col0 + tx * 4;
            #pragma unroll
            for (int j = 0; j < 4; j++)
                g_local[base + j] = acc[i][j] + bias[col0 + tx * 4 + j];
        }
    } else {
        #pragma unroll
        for (int i = 0; i < 8; i++) {
            int m = m0 + ty * 8 + i;
            int b = m >> 13, n = m & (NN - 1);
            #pragma unroll
            for (int j = 0; j < 4; j++) {
                int kcol = col0 + tx * 4 + j;
                g_S[((size_t)b * 65 + kcol) * NN + n] = acc[i][j] + bias[kcol];
            }
        }
    }
}

// ---------------- dustbin row ----------------
__global__ void k_dust(const float* __restrict__ dust) {
    int i = blockIdx.x * 256 + threadIdx.x;  // 65536
    int b = i >> 13, n = i & (NN - 1);
    g_S[((size_t)b * 65 + 64) * NN + n] = dust[0];
}

// ---------------- Sinkhorn ----------------
__global__ void k_sink_u() {
    int m = blockIdx.x, b = blockIdx.y, tid = threadIdx.x;  // 256 threads
    const float* row = &g_S[((size_t)b * 65 + m) * NN];
    const float* vb = &g_v[b * NN];
    float mx = -1e30f, sm = 0.f;
    for (int n = tid; n < NN; n += 256) {
        float xv = row[n] + vb[n];
        if (xv > mx) { sm = sm * expf(mx - xv) + 1.f; mx = xv; }
        else sm += expf(xv - mx);
    }
    __shared__ float smx[256], ssm[256];
    smx[tid] = mx; ssm[tid] = sm;
    __syncthreads();
    for (int s = 128; s > 0; s >>= 1) {
        if (tid < s) {
            float m1 = smx[tid], s1 = ssm[tid];
            float m2 = smx[tid + s], s2 = ssm[tid + s];
            if (m2 > m1) { s1 = s1 * expf(m1 - m2) + s2; m1 = m2; }
            else s1 += s2 * expf(m2 - m1);
            smx[tid] = m1; ssm[tid] = s1;
        }
        __syncthreads();
    }
    if (tid == 0) {
        float lse = smx[0] + logf(ssm[0]);
        float norm = -logf(8256.0f);
        float loga = (m == 64) ? (norm + logf(8128.0f)) : norm;
        g_u[b * 65 + m] = loga - lse;
    }
}

__global__ void k_sink_v() {
    int b = blockIdx.y;
    int n = blockIdx.x * 256 + threadIdx.x;
    __shared__ float us[65];
    if (threadIdx.x < 65) us[threadIdx.x] = g_u[b * 65 + threadIdx.x];
    __syncthreads();
    const float* col = &g_S[(size_t)b * 65 * NN + n];
    float mx = -1e30f, sm = 0.f;
    for (int m = 0; m < 65; m++) {
        float xv = col[(size_t)m * NN] + us[m];
        if (xv > mx) { sm = sm * expf(mx - xv) + 1.f; mx = xv; }
        else sm += expf(xv - mx);
    }
    g_v[b * NN + n] = -logf(8256.0f) - (mx + logf(sm));
}

__global__ void k_P() {
    int i = blockIdx.x * 256 + threadIdx.x;  // 8*64*8192
    int n = i & (NN - 1);
    int k = (i >> 13) & 63;
    int b = i >> 19;
    float lp = g_S[((size_t)b * 65 + k) * NN + n] + g_u[b * 65 + k] + g_v[b * NN + n] + logf(8256.0f);
    g_P[i] = expf(lp);
}

// ---------------- aggregation: agg[b,d,k] = sum_n local[b,n,d]*P[b,k,n] (split-K) ----------------
__global__ __launch_bounds__(256) void k_aggp() {
    int b = blockIdx.y, chunk = blockIdx.x;  // 32 chunks of 256 n
    int n0 = chunk * 256;
    int tid = threadIdx.x;
    int tx = tid & 15, ty = tid >> 4;
    int k0 = tx * 4, d0 = ty * 8;
    __shared__ float Ls[32][132];
    __shared__ float Ps[32][68];
    float acc[8][4];
    #pragma unroll
    for (int i = 0; i < 8; i++)
        #pragma unroll
        for (int j = 0; j < 4; j++) acc[i][j] = 0.f;

    for (int c = 0; c < 8; c++) {
        #pragma unroll
        for (int t = 0; t < 4; t++) {
            int f = tid + t * 256;                 // 0..1023 float4s (32n x 128d)
            int nn = f >> 5; int dq = (f & 31) * 4;
            float4 a = *reinterpret_cast<const float4*>(
                &g_local[((size_t)b * NN + n0 + c * 32 + nn) * DD + dq]);
            Ls[nn][dq + 0] = a.x; Ls[nn][dq + 1] = a.y; Ls[nn][dq + 2] = a.z; Ls[nn][dq + 3] = a.w;
        }
        #pragma unroll
        for (int t = 0; t < 2; t++) {
            int f = tid + t * 256;                 // 0..511 float4s (64k x 32n)
            int kk = f >> 3; int nq = (f & 7) * 4;
            float4 pv = *reinterpret_cast<const float4*>(
                &g_P[((size_t)b * KK + kk) * NN + n0 + c * 32 + nq]);
            Ps[nq + 0][kk] = pv.x; Ps[nq + 1][kk] = pv.y; Ps[nq + 2][kk] = pv.z; Ps[nq + 3][kk] = pv.w;
        }
        __syncthreads();
        #pragma unroll
        for (int nn = 0; nn < 32; nn++) {
            float a[8], p[4];
            #pragma unroll
            for (int i = 0; i < 8; i++) a[i] = Ls[nn][d0 + i];
            #pragma unroll
            for (int j = 0; j < 4; j++) p[j] = Ps[nn][k0 + j];
            #pragma unroll
            for (int i = 0; i < 8; i++)
                #pragma unroll
                for (int j = 0; j < 4; j++) acc[i][j] = fmaf(a[i], p[j], acc[i][j]);
        }
        __syncthreads();
    }
    float* out = &g_aggp[((size_t)(b * 32 + chunk)) * DD * KK];
    #pragma unroll
    for (int i = 0; i < 8; i++)
        #pragma unroll
        for (int j = 0; j < 4; j++)
            out[(d0 + i) * KK + k0 + j] = acc[i][j];
}

__global__ void k_aggred() {
    int i = blockIdx.x * 256 + threadIdx.x;  // 65536
    int b = i >> 13, r = i & 8191;
    float s = 0.f;
    #pragma unroll
    for (int c = 0; c < 32; c++) s += g_aggp[((size_t)(b * 32 + c)) * DD * KK + r];
    g_agg[i] = s;
}

// ---------------- final normalization ----------------
__global__ void k_final(float* __restrict__ out) {
    int b = blockIdx.x, tid = threadIdx.x;  // 256 threads
    __shared__ float red[256];
    float gtv = g_gt[b * TOKN + tid];
    red[tid] = gtv * gtv;
    __syncthreads();
    for (int s = 128; s > 0; s >>= 1) { if (tid < s) red[tid] += red[tid + s]; __syncthreads(); }
    float S1 = red[0];
    __syncthreads();
    float s2 = 0.f;
    for (int i = tid; i < DD * KK; i += 256) { float v = g_agg[b * DD * KK + i]; s2 += v * v; }
    red[tid] = s2;
    __syncthreads();
    for (int s = 128; s > 0; s >>= 1) { if (tid < s) red[tid] += red[tid + s]; __syncthreads(); }
    float S2 = red[0];
    float n1 = fmaxf(sqrtf(S1), 1e-12f);
    float n2 = fmaxf(sqrtf(S2), 1e-12f);
    float tot = fmaxf(sqrtf(S1 / (n1 * n1) + S2 / (n2 * n2)), 1e-12f);
    out[(size_t)b * OUTW + tid] = (gtv / n1) / tot;
    for (int i = tid; i < DD * KK; i += 256)
        out[(size_t)b * OUTW + TOKN + i] = (g_agg[b * DD * KK + i] / n2) / tot;
}

// ---------------- launcher ----------------
extern "C" void kernel_launch(void* const* d_in, const int* in_sizes, int n_in,
                              void* d_out, int out_size) {
    const float* x     = (const float*)d_in[0];
    const float* gem_w = (const float*)d_in[1];
    const float* dust  = (const float*)d_in[2];
    const float* tW1 = (const float*)d_in[3];  const float* tb1 = (const float*)d_in[4];
    const float* tW2 = (const float*)d_in[5];  const float* tb2 = (const float*)d_in[6];
    const float* cW1 = (const float*)d_in[7];  const float* cb1 = (const float*)d_in[8];
    const float* cW2 = (const float*)d_in[9];  const float* cb2 = (const float*)d_in[10];
    const float* sW1 = (const float*)d_in[11]; const float* sb1 = (const float*)d_in[12];
    const float* sW2 = (const float*)d_in[13]; const float* sb2 = (const float*)d_in[14];
    float* out = (float*)d_out;

    k_zero_v<<<256, 256>>>();
    k_gem_part<<<dim3(32, 8), 512>>>(x, gem_w);
    k_gem_fin<<<8, 512>>>(gem_w);
    k_tok<<<8, 512>>>(tW1, tb1, tW2, tb2);

    k_gemm1<<<dim3(8, 512), 256>>>(x, cW1, cb1, sW1, sb1);
    k_dust<<<256, 256>>>(dust);
    k_gemm2<<<dim3(2, 512), 256>>>(0, cW2, cb2, 0);    // local
    k_gemm2<<<dim3(1, 512), 256>>>(512, sW2, sb2, 1);  // scores -> S^T

    for (int it = 0; it < 3; it++) {
        k_sink_u<<<dim3(65, 8), 256>>>();
        k_sink_v<<<dim3(32, 8), 256>>>();
    }
    k_P<<<16384, 256>>>();

    k_aggp<<<dim3(32, 8), 256>>>();
    k_aggred<<<256, 256>>>();
    k_final<<<8, 256>>>(out);
}

// round 2
// speedup vs baseline: 1.7624x; 1.7624x over previous
#include <cuda_runtime.h>
#include <math.h>
#include <stdint.h>

// ---------------- problem constants ----------------
#define BB 8
#define NN 8192
#define CC 512
#define KK 64
#define DD 128
#define TOKN 256
#define MTOT (BB*NN)          // 65536
#define HDIM 1024             // concat hidden (c: 0..511, s: 512..1023)
#define OUTW (TOKN + DD*KK)   // 8448

// ---------------- scratch (device globals) ----------------
__device__ float g_H[(size_t)MTOT * HDIM];          // layer-1 activations
__device__ float g_S[(size_t)BB * 65 * NN];         // augmented score matrix [b,65,n]
__device__ float g_P[(size_t)BB * KK * NN];         // matching probs
__device__ float g_local[(size_t)MTOT * DD];        // local features
__device__ float g_u[BB * 65];
__device__ float g_v[BB * NN];
__device__ float g_gp[BB * 32 * CC];                // GeM partials
__device__ float g_g[BB * CC];                      // GeM pooled
__device__ float g_h1[BB * 512];                    // token MLP hidden
__device__ float g_gt[BB * TOKN];                   // global token
__device__ float g_aggp[(size_t)BB * 32 * DD * KK]; // agg split-K partials
__device__ float g_agg[BB * DD * KK];

__device__ __forceinline__ float compute_p(float w) {
    float sp = (w > 20.f) ? w : log1pf(expf(w));
    return fminf(sp + 1e-3f, 10.0f);
}

__device__ __forceinline__ uint32_t f2tf32(float x) {
    uint32_t r;
    asm("cvt.rna.tf32.f32 %0, %1;" : "=r"(r) : "f"(x));
    return r;
}

__device__ __forceinline__ void mma_tf32(float* d, const uint32_t* a, const uint32_t* b) {
    asm volatile(
        "mma.sync.aligned.m16n8k8.row.col.f32.tf32.tf32.f32 "
        "{%0,%1,%2,%3}, {%4,%5,%6,%7}, {%8,%9}, {%0,%1,%2,%3};\n"
        : "+f"(d[0]), "+f"(d[1]), "+f"(d[2]), "+f"(d[3])
        : "r"(a[0]), "r"(a[1]), "r"(a[2]), "r"(a[3]), "r"(b[0]), "r"(b[1]));
}

// ---------------- init ----------------
__global__ void k_zero_v() {
    int i = blockIdx.x * 256 + threadIdx.x;
    g_v[i] = 0.f;
}

// ---------------- GeM pooling ----------------
__global__ void k_gem_part(const float* __restrict__ x, const float* __restrict__ gem_w) {
    int b = blockIdx.y, part = blockIdx.x, c = threadIdx.x;
    float p = compute_p(gem_w[0]);
    bool cube = fabsf(p - 3.0f) < 1e-5f;
    const float* xp = x + ((size_t)b * NN + part * 256) * CC + c;
    float s = 0.f;
    if (cube) {
        #pragma unroll 4
        for (int n = 0; n < 256; n++) {
            float v = fmaxf(xp[(size_t)n * CC], 1e-6f);
            s += v * v * v;
        }
    } else {
        for (int n = 0; n < 256; n++) {
            float v = fmaxf(xp[(size_t)n * CC], 1e-6f);
            s += __powf(v, p);
        }
    }
    g_gp[(b * 32 + part) * CC + c] = s;
}

__global__ void k_gem_fin(const float* __restrict__ gem_w) {
    int b = blockIdx.x, c = threadIdx.x;
    float s = 0.f;
    #pragma unroll
    for (int i = 0; i < 32; i++) s += g_gp[(b * 32 + i) * CC + c];
    float p = compute_p(gem_w[0]);
    float mean = s * (1.0f / (float)NN);
    float g = powf(mean, 1.0f / p);
    if (!isfinite(g)) g = 0.f;
    g_g[b * CC + c] = g;
}

// ---------------- token MLP: warp per output ----------------
__global__ void k_tok1(const float* __restrict__ tW1, const float* __restrict__ tb1) {
    int warp = blockIdx.x * 8 + (threadIdx.x >> 5);   // 0..4095
    int lane = threadIdx.x & 31;
    int b = warp >> 9, t = warp & 511;
    const float* g = &g_g[b * CC];
    const float* w = tW1 + (size_t)t * CC;
    float s = 0.f;
    #pragma unroll
    for (int c = lane; c < CC; c += 32) s = fmaf(g[c], w[c], s);
    #pragma unroll
    for (int o = 16; o > 0; o >>= 1) s += __shfl_xor_sync(0xffffffffu, s, o);
    if (lane == 0) g_h1[b * 512 + t] = fmaxf(s + tb1[t], 0.f);
}

__global__ void k_tok2(const float* __restrict__ tW2, const float* __restrict__ tb2) {
    int warp = blockIdx.x * 8 + (threadIdx.x >> 5);   // 0..2047
    int lane = threadIdx.x & 31;
    int b = warp >> 8, t = warp & 255;
    const float* h = &g_h1[b * 512];
    const float* w = tW2 + (size_t)t * 512;
    float s = 0.f;
    #pragma unroll
    for (int c = lane; c < 512; c += 32) s = fmaf(h[c], w[c], s);
    #pragma unroll
    for (int o = 16; o > 0; o >>= 1) s += __shfl_xor_sync(0xffffffffu, s, o);
    if (lane == 0) g_gt[b * TOKN + t] = s + tb2[t];
}

// ---------------- layer-1 GEMM (tf32 mma): H = relu(X @ [cW1;sW1]^T + b) ----------------
// BM=128 BN=128 BK=16, 256 threads (8 warps 2x4), warp tile 64x32
__global__ __launch_bounds__(256) void k_gemm1_mma(const float* __restrict__ X,
                                                   const float* __restrict__ Wc, const float* __restrict__ bc,
                                                   const float* __restrict__ Ws, const float* __restrict__ bs) {
    __shared__ uint32_t As[2][16][136];
    __shared__ uint32_t Bs[2][16][136];
    int tid = threadIdx.x;
    int warpid = tid >> 5, lane = tid & 31;
    int g = lane >> 2, l4 = lane & 3;
    int wm = (warpid >> 2) * 64;     // 0 or 64
    int wn = (warpid & 3) * 32;      // 0,32,64,96
    int m0 = blockIdx.y * 128;
    int col0 = blockIdx.x * 128;
    const float* W    = (col0 < 512) ? (Wc + (size_t)col0 * CC) : (Ws + (size_t)(col0 - 512) * CC);
    const float* bias = (col0 < 512) ? (bc + col0) : (bs + (col0 - 512));

    float acc[4][4][4];
    #pragma unroll
    for (int i = 0; i < 4; i++)
        #pragma unroll
        for (int j = 0; j < 4; j++)
            #pragma unroll
            for (int r = 0; r < 4; r++) acc[i][j][r] = 0.f;

    float4 av[2], bv[2];
    int f0 = tid, f1 = tid + 256;
    int k4a0 = f0 >> 7, ma0 = f0 & 127;
    int k4a1 = f1 >> 7, ma1 = f1 & 127;

    // prologue load kb=0
    {
        av[0] = *(const float4*)(X + (size_t)(m0 + ma0) * CC + k4a0 * 4);
        av[1] = *(const float4*)(X + (size_t)(m0 + ma1) * CC + k4a1 * 4);
        bv[0] = *(const float4*)(W + (size_t)ma0 * CC + k4a0 * 4);
        bv[1] = *(const float4*)(W + (size_t)ma1 * CC + k4a1 * 4);
        As[0][k4a0 * 4 + 0][ma0] = f2tf32(av[0].x); As[0][k4a0 * 4 + 1][ma0] = f2tf32(av[0].y);
        As[0][k4a0 * 4 + 2][ma0] = f2tf32(av[0].z); As[0][k4a0 * 4 + 3][ma0] = f2tf32(av[0].w);
        As[0][k4a1 * 4 + 0][ma1] = f2tf32(av[1].x); As[0][k4a1 * 4 + 1][ma1] = f2tf32(av[1].y);
        As[0][k4a1 * 4 + 2][ma1] = f2tf32(av[1].z); As[0][k4a1 * 4 + 3][ma1] = f2tf32(av[1].w);
        Bs[0][k4a0 * 4 + 0][ma0] = f2tf32(bv[0].x); Bs[0][k4a0 * 4 + 1][ma0] = f2tf32(bv[0].y);
        Bs[0][k4a0 * 4 + 2][ma0] = f2tf32(bv[0].z); Bs[0][k4a0 * 4 + 3][ma0] = f2tf32(bv[0].w);
        Bs[0][k4a1 * 4 + 0][ma1] = f2tf32(bv[1].x); Bs[0][k4a1 * 4 + 1][ma1] = f2tf32(bv[1].y);
        Bs[0][k4a1 * 4 + 2][ma1] = f2tf32(bv[1].z); Bs[0][k4a1 * 4 + 3][ma1] = f2tf32(bv[1].w);
    }
    __syncthreads();

    const int NKB = CC / 16;  // 32
    for (int kb = 0; kb < NKB; kb++) {
        int s = kb & 1;
        if (kb + 1 < NKB) {
            int ko = (kb + 1) * 16;
            av[0] = *(const float4*)(X + (size_t)(m0 + ma0) * CC + ko + k4a0 * 4);
            av[1] = *(const float4*)(X + (size_t)(m0 + ma1) * CC + ko + k4a1 * 4);
            bv[0] = *(const float4*)(W + (size_t)ma0 * CC + ko + k4a0 * 4);
            bv[1] = *(const float4*)(W + (size_t)ma1 * CC + ko + k4a1 * 4);
        }
        #pragma unroll
        for (int kk = 0; kk < 2; kk++) {
            int k0 = kk * 8;
            uint32_t a[4][4], b[4][2];
            #pragma unroll
            for (int i = 0; i < 4; i++) {
                int mb = wm + i * 16 + g;
                a[i][0] = As[s][k0 + l4][mb];
                a[i][1] = As[s][k0 + l4][mb + 8];
                a[i][2] = As[s][k0 + l4 + 4][mb];
                a[i][3] = As[s][k0 + l4 + 4][mb + 8];
            }
            #pragma unroll
            for (int j = 0; j < 4; j++) {
                int nb = wn + j * 8 + g;
                b[j][0] = Bs[s][k0 + l4][nb];
                b[j][1] = Bs[s][k0 + l4 + 4][nb];
            }
            #pragma unroll
            for (int i = 0; i < 4; i++)
                #pragma unroll
                for (int j = 0; j < 4; j++)
                    mma_tf32(acc[i][j], a[i], b[j]);
        }
        if (kb + 1 < NKB) {
            int ns = (kb + 1) & 1;
            As[ns][k4a0 * 4 + 0][ma0] = f2tf32(av[0].x); As[ns][k4a0 * 4 + 1][ma0] = f2tf32(av[0].y);
            As[ns][k4a0 * 4 + 2][ma0] = f2tf32(av[0].z); As[ns][k4a0 * 4 + 3][ma0] = f2tf32(av[0].w);
            As[ns][k4a1 * 4 + 0][ma1] = f2tf32(av[1].x); As[ns][k4a1 * 4 + 1][ma1] = f2tf32(av[1].y);
            As[ns][k4a1 * 4 + 2][ma1] = f2tf32(av[1].z); As[ns][k4a1 * 4 + 3][ma1] = f2tf32(av[1].w);
            Bs[ns][k4a0 * 4 + 0][ma0] = f2tf32(bv[0].x); Bs[ns][k4a0 * 4 + 1][ma0] = f2tf32(bv[0].y);
            Bs[ns][k4a0 * 4 + 2][ma0] = f2tf32(bv[0].z); Bs[ns][k4a0 * 4 + 3][ma0] = f2tf32(bv[0].w);
            Bs[ns][k4a1 * 4 + 0][ma1] = f2tf32(bv[1].x); Bs[ns][k4a1 * 4 + 1][ma1] = f2tf32(bv[1].y);
            Bs[ns][k4a1 * 4 + 2][ma1] = f2tf32(bv[1].z); Bs[ns][k4a1 * 4 + 3][ma1] = f2tf32(bv[1].w);
        }
        __syncthreads();
    }

    // epilogue: bias + relu -> g_H
    #pragma unroll
    for (int i = 0; i < 4; i++) {
        #pragma unroll
        for (int j = 0; j < 4; j++) {
            int col = wn + j * 8 + l4 * 2;
            float b0 = bias[col], b1 = bias[col + 1];
            int r0 = m0 + wm + i * 16 + g;
            size_t base0 = (size_t)r0 * HDIM + col0 + col;
            size_t base1 = (size_t)(r0 + 8) * HDIM + col0 + col;
            g_H[base0 + 0] = fmaxf(acc[i][j][0] + b0, 0.f);
            g_H[base0 + 1] = fmaxf(acc[i][j][1] + b1, 0.f);
            g_H[base1 + 0] = fmaxf(acc[i][j][2] + b0, 0.f);
            g_H[base1 + 1] = fmaxf(acc[i][j][3] + b1, 0.f);
        }
    }
}

// ---------------- layer-2 GEMM (tf32 mma, BN=64) ----------------
// BM=128 BN=64 BK=16, 256 threads (8 warps 4x2), warp tile 32x32
__global__ __launch_bounds__(256) void k_gemm2_mma(int aoff,
                                                   const float* __restrict__ W, const float* __restrict__ bias,
                                                   int outMode) {
    __shared__ uint32_t As[2][16][136];
    __shared__ uint32_t Bs[2][16][72];
    int tid = threadIdx.x;
    int warpid = tid >> 5, lane = tid & 31;
    int g = lane >> 2, l4 = lane & 3;
    int wm = (warpid >> 1) * 32;     // 0,32,64,96
    int wn = (warpid & 1) * 32;      // 0,32
    int m0 = blockIdx.y * 128;
    int col0 = blockIdx.x * 64;

    float acc[2][4][4];
    #pragma unroll
    for (int i = 0; i < 2; i++)
        #pragma unroll
        for (int j = 0; j < 4; j++)
            #pragma unroll
            for (int r = 0; r < 4; r++) acc[i][j][r] = 0.f;

    float4 av[2], bv;
    int f0 = tid, f1 = tid + 256;
    int k4a0 = f0 >> 7, ma0 = f0 & 127;
    int k4a1 = f1 >> 7, ma1 = f1 & 127;
    int k4b = tid >> 6, nb0 = tid & 63;

    {
        av[0] = *(const float4*)(&g_H[(size_t)(m0 + ma0) * HDIM + aoff + k4a0 * 4]);
        av[1] = *(const float4*)(&g_H[(size_t)(m0 + ma1) * HDIM + aoff + k4a1 * 4]);
        bv    = *(const float4*)(W + (size_t)(col0 + nb0) * CC + k4b * 4);
        As[0][k4a0 * 4 + 0][ma0] = f2tf32(av[0].x); As[0][k4a0 * 4 + 1][ma0] = f2tf32(av[0].y);
        As[0][k4a0 * 4 + 2][ma0] = f2tf32(av[0].z); As[0][k4a0 * 4 + 3][ma0] = f2tf32(av[0].w);
        As[0][k4a1 * 4 + 0][ma1] = f2tf32(av[1].x); As[0][k4a1 * 4 + 1][ma1] = f2tf32(av[1].y);
        As[0][k4a1 * 4 + 2][ma1] = f2tf32(av[1].z); As[0][k4a1 * 4 + 3][ma1] = f2tf32(av[1].w);
        Bs[0][k4b * 4 + 0][nb0] = f2tf32(bv.x); Bs[0][k4b * 4 + 1][nb0] = f2tf32(bv.y);
        Bs[0][k4b * 4 + 2][nb0] = f2tf32(bv.z); Bs[0][k4b * 4 + 3][nb0] = f2tf32(bv.w);
    }
    __syncthreads();

    const int NKB = CC / 16;
    for (int kb = 0; kb < NKB; kb++) {
        int s = kb & 1;
        if (kb + 1 < NKB) {
            int ko = (kb + 1) * 16;
            av[0] = *(const float4*)(&g_H[(size_t)(m0 + ma0) * HDIM + aoff + ko + k4a0 * 4]);
            av[1] = *(const float4*)(&g_H[(size_t)(m0 + ma1) * HDIM + aoff + ko + k4a1 * 4]);
            bv    = *(const float4*)(W + (size_t)(col0 + nb0) * CC + ko + k4b * 4);
        }
        #pragma unroll
        for (int kk = 0; kk < 2; kk++) {
            int k0 = kk * 8;
            uint32_t a[2][4], b[4][2];
            #pragma unroll
            for (int i = 0; i < 2; i++) {
                int mb = wm + i * 16 + g;
                a[i][0] = As[s][k0 + l4][mb];
                a[i][1] = As[s][k0 + l4][mb + 8];
                a[i][2] = As[s][k0 + l4 + 4][mb];
                a[i][3] = As[s][k0 + l4 + 4][mb + 8];
            }
            #pragma unroll
            for (int j = 0; j < 4; j++) {
                int nb = wn + j * 8 + g;
                b[j][0] = Bs[s][k0 + l4][nb];
                b[j][1] = Bs[s][k0 + l4 + 4][nb];
            }
            #pragma unroll
            for (int i = 0; i < 2; i++)
                #pragma unroll
                for (int j = 0; j < 4; j++)
                    mma_tf32(acc[i][j], a[i], b[j]);
        }
        if (kb + 1 < NKB) {
            int ns = (kb + 1) & 1;
            As[ns][k4a0 * 4 + 0][ma0] = f2tf32(av[0].x); As[ns][k4a0 * 4 + 1][ma0] = f2tf32(av[0].y);
            As[ns][k4a0 * 4 + 2][ma0] = f2tf32(av[0].z); As[ns][k4a0 * 4 + 3][ma0] = f2tf32(av[0].w);
            As[ns][k4a1 * 4 + 0][ma1] = f2tf32(av[1].x); As[ns][k4a1 * 4 + 1][ma1] = f2tf32(av[1].y);
            As[ns][k4a1 * 4 + 2][ma1] = f2tf32(av[1].z); As[ns][k4a1 * 4 + 3][ma1] = f2tf32(av[1].w);
            Bs[ns][k4b * 4 + 0][nb0] = f2tf32(bv.x); Bs[ns][k4b * 4 + 1][nb0] = f2tf32(bv.y);
            Bs[ns][k4b * 4 + 2][nb0] = f2tf32(bv.z); Bs[ns][k4b * 4 + 3][nb0] = f2tf32(bv.w);
        }
        __syncthreads();
    }

    #pragma unroll
    for (int i = 0; i < 2; i++) {
        #pragma unroll
        for (int j = 0; j < 4; j++) {
            int col = wn + j * 8 + l4 * 2;
            float b0 = bias[col0 + col], b1 = bias[col0 + col + 1];
            int r0 = m0 + wm + i * 16 + g;
            if (outMode == 0) {
                size_t base0 = (size_t)r0 * DD + col0 + col;
                size_t base1 = (size_t)(r0 + 8) * DD + col0 + col;
                g_local[base0 + 0] = acc[i][j][0] + b0;
                g_local[base0 + 1] = acc[i][j][1] + b1;
                g_local[base1 + 0] = acc[i][j][2] + b0;
                g_local[base1 + 1] = acc[i][j][3] + b1;
            } else {
                int b0i = r0 >> 13, n0i = r0 & (NN - 1);
                int b1i = (r0 + 8) >> 13, n1i = (r0 + 8) & (NN - 1);
                g_S[((size_t)b0i * 65 + col0 + col + 0) * NN + n0i] = acc[i][j][0] + b0;
                g_S[((size_t)b0i * 65 + col0 + col + 1) * NN + n0i] = acc[i][j][1] + b1;
                g_S[((size_t)b1i * 65 + col0 + col + 0) * NN + n1i] = acc[i][j][2] + b0;
                g_S[((size_t)b1i * 65 + col0 + col + 1) * NN + n1i] = acc[i][j][3] + b1;
            }
        }
    }
}

// ---------------- dustbin row ----------------
__global__ void k_dust(const float* __restrict__ dust) {
    int i = blockIdx.x * 256 + threadIdx.x;
    int b = i >> 13, n = i & (NN - 1);
    g_S[((size_t)b * 65 + 64) * NN + n] = dust[0];
}

// ---------------- Sinkhorn ----------------
__global__ void k_sink_u() {
    int m = blockIdx.x, b = blockIdx.y, tid = threadIdx.x;
    const float* row = &g_S[((size_t)b * 65 + m) * NN];
    const float* vb = &g_v[b * NN];
    float mx = -1e30f, sm = 0.f;
    for (int n = tid; n < NN; n += 256) {
        float xv = row[n] + vb[n];
        if (xv > mx) { sm = sm * expf(mx - xv) + 1.f; mx = xv; }
        else sm += expf(xv - mx);
    }
    __shared__ float smx[256], ssm[256];
    smx[tid] = mx; ssm[tid] = sm;
    __syncthreads();
    for (int s = 128; s > 0; s >>= 1) {
        if (tid < s) {
            float m1 = smx[tid], s1 = ssm[tid];
            float m2 = smx[tid + s], s2 = ssm[tid + s];
            if (m2 > m1) { s1 = s1 * expf(m1 - m2) + s2; m1 = m2; }
            else s1 += s2 * expf(m2 - m1);
            smx[tid] = m1; ssm[tid] = s1;
        }
        __syncthreads();
    }
    if (tid == 0) {
        float lse = smx[0] + logf(ssm[0]);
        float norm = -logf(8256.0f);
        float loga = (m == 64) ? (norm + logf(8128.0f)) : norm;
        g_u[b * 65 + m] = loga - lse;
    }
}

__global__ void k_sink_v() {
    int b = blockIdx.y;
    int n = blockIdx.x * 256 + threadIdx.x;
    __shared__ float us[65];
    if (threadIdx.x < 65) us[threadIdx.x] = g_u[b * 65 + threadIdx.x];
    __syncthreads();
    const float* col = &g_S[(size_t)b * 65 * NN + n];
    float mx = -1e30f, sm = 0.f;
    for (int m = 0; m < 65; m++) {
        float xv = col[(size_t)m * NN] + us[m];
        if (xv > mx) { sm = sm * expf(mx - xv) + 1.f; mx = xv; }
        else sm += expf(xv - mx);
    }
    g_v[b * NN + n] = -logf(8256.0f) - (mx + logf(sm));
}

__global__ void k_P() {
    int i = blockIdx.x * 256 + threadIdx.x;
    int n = i & (NN - 1);
    int k = (i >> 13) & 63;
    int b = i >> 19;
    float lp = g_S[((size_t)b * 65 + k) * NN + n] + g_u[b * 65 + k] + g_v[b * NN + n] + logf(8256.0f);
    g_P[i] = expf(lp);
}

// ---------------- aggregation ----------------
__global__ __launch_bounds__(256) void k_aggp() {
    int b = blockIdx.y, chunk = blockIdx.x;
    int n0 = chunk * 256;
    int tid = threadIdx.x;
    int tx = tid & 15, ty = tid >> 4;
    int k0 = tx * 4, d0 = ty * 8;
    __shared__ float Ls[32][132];
    __shared__ float Ps[32][68];
    float acc[8][4];
    #pragma unroll
    for (int i = 0; i < 8; i++)
        #pragma unroll
        for (int j = 0; j < 4; j++) acc[i][j] = 0.f;

    for (int c = 0; c < 8; c++) {
        #pragma unroll
        for (int t = 0; t < 4; t++) {
            int f = tid + t * 256;
            int nn = f >> 5; int dq = (f & 31) * 4;
            float4 a = *reinterpret_cast<const float4*>(
                &g_local[((size_t)b * NN + n0 + c * 32 + nn) * DD + dq]);
            Ls[nn][dq + 0] = a.x; Ls[nn][dq + 1] = a.y; Ls[nn][dq + 2] = a.z; Ls[nn][dq + 3] = a.w;
        }
        #pragma unroll
        for (int t = 0; t < 2; t++) {
            int f = tid + t * 256;
            int kk = f >> 3; int nq = (f & 7) * 4;
            float4 pv = *reinterpret_cast<const float4*>(
                &g_P[((size_t)b * KK + kk) * NN + n0 + c * 32 + nq]);
            Ps[nq + 0][kk] = pv.x; Ps[nq + 1][kk] = pv.y; Ps[nq + 2][kk] = pv.z; Ps[nq + 3][kk] = pv.w;
        }
        __syncthreads();
        #pragma unroll
        for (int nn = 0; nn < 32; nn++) {
            float a[8], p[4];
            #pragma unroll
            for (int i = 0; i < 8; i++) a[i] = Ls[nn][d0 + i];
            #pragma unroll
            for (int j = 0; j < 4; j++) p[j] = Ps[nn][k0 + j];
            #pragma unroll
            for (int i = 0; i < 8; i++)
                #pragma unroll
                for (int j = 0; j < 4; j++) acc[i][j] = fmaf(a[i], p[j], acc[i][j]);
        }
        __syncthreads();
    }
    float* out = &g_aggp[((size_t)(b * 32 + chunk)) * DD * KK];
    #pragma unroll
    for (int i = 0; i < 8; i++)
        #pragma unroll
        for (int j = 0; j < 4; j++)
            out[(d0 + i) * KK + k0 + j] = acc[i][j];
}

__global__ void k_aggred() {
    int i = blockIdx.x * 256 + threadIdx.x;
    int b = i >> 13, r = i & 8191;
    float s = 0.f;
    #pragma unroll
    for (int c = 0; c < 32; c++) s += g_aggp[((size_t)(b * 32 + c)) * DD * KK + r];
    g_agg[i] = s;
}

// ---------------- final normalization ----------------
__global__ void k_final(float* __restrict__ out) {
    int b = blockIdx.x, tid = threadIdx.x;
    __shared__ float red[256];
    float gtv = g_gt[b * TOKN + tid];
    red[tid] = gtv * gtv;
    __syncthreads();
    for (int s = 128; s > 0; s >>= 1) { if (tid < s) red[tid] += red[tid + s]; __syncthreads(); }
    float S1 = red[0];
    __syncthreads();
    float s2 = 0.f;
    for (int i = tid; i < DD * KK; i += 256) { float v = g_agg[b * DD * KK + i]; s2 += v * v; }
    red[tid] = s2;
    __syncthreads();
    for (int s = 128; s > 0; s >>= 1) { if (tid < s) red[tid] += red[tid + s]; __syncthreads(); }
    float S2 = red[0];
    float n1 = fmaxf(sqrtf(S1), 1e-12f);
    float n2 = fmaxf(sqrtf(S2), 1e-12f);
    float tot = fmaxf(sqrtf(S1 / (n1 * n1) + S2 / (n2 * n2)), 1e-12f);
    out[(size_t)b * OUTW + tid] = (gtv / n1) / tot;
    for (int i = tid; i < DD * KK; i += 256)
        out[(size_t)b * OUTW + TOKN + i] = (g_agg[b * DD * KK + i] / n2) / tot;
}

// ---------------- launcher ----------------
extern "C" void kernel_launch(void* const* d_in, const int* in_sizes, int n_in,
                              void* d_out, int out_size) {
    const float* x     = (const float*)d_in[0];
    const float* gem_w = (const float*)d_in[1];
    const float* dust  = (const float*)d_in[2];
    const float* tW1 = (const float*)d_in[3];  const float* tb1 = (const float*)d_in[4];
    const float* tW2 = (const float*)d_in[5];  const float* tb2 = (const float*)d_in[6];
    const float* cW1 = (const float*)d_in[7];  const float* cb1 = (const float*)d_in[8];
    const float* cW2 = (const float*)d_in[9];  const float* cb2 = (const float*)d_in[10];
    const float* sW1 = (const float*)d_in[11]; const float* sb1 = (const float*)d_in[12];
    const float* sW2 = (const float*)d_in[13]; const float* sb2 = (const float*)d_in[14];
    float* out = (float*)d_out;

    k_zero_v<<<256, 256>>>();
    k_gem_part<<<dim3(32, 8), 512>>>(x, gem_w);
    k_gem_fin<<<8, 512>>>(gem_w);
    k_tok1<<<512, 256>>>(tW1, tb1);
    k_tok2<<<256, 256>>>(tW2, tb2);

    k_gemm1_mma<<<dim3(8, 512), 256>>>(x, cW1, cb1, sW1, sb1);
    k_dust<<<256, 256>>>(dust);
    k_gemm2_mma<<<dim3(2, 512), 256>>>(0, cW2, cb2, 0);    // local
    k_gemm2_mma<<<dim3(1, 512), 256>>>(512, sW2, sb2, 1);  // scores -> S^T

    for (int it = 0; it < 3; it++) {
        k_sink_u<<<dim3(65, 8), 256>>>();
        k_sink_v<<<dim3(32, 8), 256>>>();
    }
    k_P<<<16384, 256>>>();

    k_aggp<<<dim3(32, 8), 256>>>();
    k_aggred<<<256, 256>>>();
    k_final<<<8, 256>>>(out);
}

// round 3
// speedup vs baseline: 1.7634x; 1.0006x over previous
#include <cuda_runtime.h>
#include <math.h>
#include <stdint.h>

// ---------------- problem constants ----------------
#define BB 8
#define NN 8192
#define CC 512
#define KK 64
#define DD 128
#define TOKN 256
#define MTOT (BB*NN)          // 65536
#define HDIM 1024             // concat hidden (c: 0..511, s: 512..1023)
#define OUTW (TOKN + DD*KK)   // 8448

// ---------------- scratch (device globals) ----------------
__device__ float g_H[(size_t)MTOT * HDIM];          // layer-1 activations
__device__ float g_S[(size_t)BB * 65 * NN];         // augmented score matrix [b,65,n]
__device__ float g_P[(size_t)BB * KK * NN];         // matching probs
__device__ float g_local[(size_t)MTOT * DD];        // local features
__device__ float g_u[BB * 65];
__device__ float g_v[BB * NN];
__device__ float g_gp[BB * 32 * CC];                // GeM partials
__device__ float g_g[BB * CC];                      // GeM pooled
__device__ float g_h1[BB * 512];                    // token MLP hidden
__device__ float g_gt[BB * TOKN];                   // global token
__device__ float g_aggp[(size_t)BB * 32 * DD * KK]; // agg split-K partials
__device__ float g_agg[BB * DD * KK];

__device__ __forceinline__ float compute_p(float w) {
    float sp = (w > 20.f) ? w : log1pf(expf(w));
    return fminf(sp + 1e-3f, 10.0f);
}

__device__ __forceinline__ uint32_t f2tf32(float x) {
    uint32_t r;
    asm("cvt.rna.tf32.f32 %0, %1;" : "=r"(r) : "f"(x));
    return r;
}

__device__ __forceinline__ void mma_tf32(float* d, const uint32_t* a, const uint32_t* b) {
    asm volatile(
        "mma.sync.aligned.m16n8k8.row.col.f32.tf32.tf32.f32 "
        "{%0,%1,%2,%3}, {%4,%5,%6,%7}, {%8,%9}, {%0,%1,%2,%3};\n"
        : "+f"(d[0]), "+f"(d[1]), "+f"(d[2]), "+f"(d[3])
        : "r"(a[0]), "r"(a[1]), "r"(a[2]), "r"(a[3]), "r"(b[0]), "r"(b[1]));
}

// ---------------- init ----------------
__global__ void k_zero_v() {
    int i = blockIdx.x * 256 + threadIdx.x;
    g_v[i] = 0.f;
}

// ---------------- GeM pooling ----------------
__global__ void k_gem_part(const float* __restrict__ x, const float* __restrict__ gem_w) {
    int b = blockIdx.y, part = blockIdx.x, c = threadIdx.x;
    float p = compute_p(gem_w[0]);
    bool cube = fabsf(p - 3.0f) < 1e-5f;
    const float* xp = x + ((size_t)b * NN + part * 256) * CC + c;
    float s = 0.f;
    if (cube) {
        #pragma unroll 4
        for (int n = 0; n < 256; n++) {
            float v = fmaxf(xp[(size_t)n * CC], 1e-6f);
            s += v * v * v;
        }
    } else {
        for (int n = 0; n < 256; n++) {
            float v = fmaxf(xp[(size_t)n * CC], 1e-6f);
            s += __powf(v, p);
        }
    }
    g_gp[(b * 32 + part) * CC + c] = s;
}

__global__ void k_gem_fin(const float* __restrict__ gem_w) {
    int b = blockIdx.x, c = threadIdx.x;
    float s = 0.f;
    #pragma unroll
    for (int i = 0; i < 32; i++) s += g_gp[(b * 32 + i) * CC + c];
    float p = compute_p(gem_w[0]);
    float mean = s * (1.0f / (float)NN);
    float g = powf(mean, 1.0f / p);
    if (!isfinite(g)) g = 0.f;
    g_g[b * CC + c] = g;
}

// ---------------- token MLP: warp per output ----------------
__global__ void k_tok1(const float* __restrict__ tW1, const float* __restrict__ tb1) {
    int warp = blockIdx.x * 8 + (threadIdx.x >> 5);   // 0..4095
    int lane = threadIdx.x & 31;
    int b = warp >> 9, t = warp & 511;
    const float* g = &g_g[b * CC];
    const float* w = tW1 + (size_t)t * CC;
    float s = 0.f;
    #pragma unroll
    for (int c = lane; c < CC; c += 32) s = fmaf(g[c], w[c], s);
    #pragma unroll
    for (int o = 16; o > 0; o >>= 1) s += __shfl_xor_sync(0xffffffffu, s, o);
    if (lane == 0) g_h1[b * 512 + t] = fmaxf(s + tb1[t], 0.f);
}

__global__ void k_tok2(const float* __restrict__ tW2, const float* __restrict__ tb2) {
    int warp = blockIdx.x * 8 + (threadIdx.x >> 5);   // 0..2047
    int lane = threadIdx.x & 31;
    int b = warp >> 8, t = warp & 255;
    const float* h = &g_h1[b * 512];
    const float* w = tW2 + (size_t)t * 512;
    float s = 0.f;
    #pragma unroll
    for (int c = lane; c < 512; c += 32) s = fmaf(h[c], w[c], s);
    #pragma unroll
    for (int o = 16; o > 0; o >>= 1) s += __shfl_xor_sync(0xffffffffu, s, o);
    if (lane == 0) g_gt[b * TOKN + t] = s + tb2[t];
}

// ---------------- layer-1 GEMM (tf32 mma): H = relu(X @ [cW1;sW1]^T + b) ----------------
// BM=128 BN=128 BK=16, 256 threads (8 warps 2x4), warp tile 64x32
__global__ __launch_bounds__(256) void k_gemm1_mma(const float* __restrict__ X,
                                                   const float* __restrict__ Wc, const float* __restrict__ bc,
                                                   const float* __restrict__ Ws, const float* __restrict__ bs) {
    __shared__ uint32_t As[2][16][136];
    __shared__ uint32_t Bs[2][16][136];
    int tid = threadIdx.x;
    int warpid = tid >> 5, lane = tid & 31;
    int g = lane >> 2, l4 = lane & 3;
    int wm = (warpid >> 2) * 64;     // 0 or 64
    int wn = (warpid & 3) * 32;      // 0,32,64,96
    int m0 = blockIdx.y * 128;
    int col0 = blockIdx.x * 128;
    const float* W    = (col0 < 512) ? (Wc + (size_t)col0 * CC) : (Ws + (size_t)(col0 - 512) * CC);
    const float* bias = (col0 < 512) ? (bc + col0) : (bs + (col0 - 512));

    float acc[4][4][4];
    #pragma unroll
    for (int i = 0; i < 4; i++)
        #pragma unroll
        for (int j = 0; j < 4; j++)
            #pragma unroll
            for (int r = 0; r < 4; r++) acc[i][j][r] = 0.f;

    float4 av[2], bv[2];
    int f0 = tid, f1 = tid + 256;
    int k4a0 = f0 >> 7, ma0 = f0 & 127;
    int k4a1 = f1 >> 7, ma1 = f1 & 127;

    // prologue load kb=0
    {
        av[0] = *(const float4*)(X + (size_t)(m0 + ma0) * CC + k4a0 * 4);
        av[1] = *(const float4*)(X + (size_t)(m0 + ma1) * CC + k4a1 * 4);
        bv[0] = *(const float4*)(W + (size_t)ma0 * CC + k4a0 * 4);
        bv[1] = *(const float4*)(W + (size_t)ma1 * CC + k4a1 * 4);
        As[0][k4a0 * 4 + 0][ma0] = f2tf32(av[0].x); As[0][k4a0 * 4 + 1][ma0] = f2tf32(av[0].y);
        As[0][k4a0 * 4 + 2][ma0] = f2tf32(av[0].z); As[0][k4a0 * 4 + 3][ma0] = f2tf32(av[0].w);
        As[0][k4a1 * 4 + 0][ma1] = f2tf32(av[1].x); As[0][k4a1 * 4 + 1][ma1] = f2tf32(av[1].y);
        As[0][k4a1 * 4 + 2][ma1] = f2tf32(av[1].z); As[0][k4a1 * 4 + 3][ma1] = f2tf32(av[1].w);
        Bs[0][k4a0 * 4 + 0][ma0] = f2tf32(bv[0].x); Bs[0][k4a0 * 4 + 1][ma0] = f2tf32(bv[0].y);
        Bs[0][k4a0 * 4 + 2][ma0] = f2tf32(bv[0].z); Bs[0][k4a0 * 4 + 3][ma0] = f2tf32(bv[0].w);
        Bs[0][k4a1 * 4 + 0][ma1] = f2tf32(bv[1].x); Bs[0][k4a1 * 4 + 1][ma1] = f2tf32(bv[1].y);
        Bs[0][k4a1 * 4 + 2][ma1] = f2tf32(bv[1].z); Bs[0][k4a1 * 4 + 3][ma1] = f2tf32(bv[1].w);
    }
    __syncthreads();

    const int NKB = CC / 16;  // 32
    for (int kb = 0; kb < NKB; kb++) {
        int s = kb & 1;
        if (kb + 1 < NKB) {
            int ko = (kb + 1) * 16;
            av[0] = *(const float4*)(X + (size_t)(m0 + ma0) * CC + ko + k4a0 * 4);
            av[1] = *(const float4*)(X + (size_t)(m0 + ma1) * CC + ko + k4a1 * 4);
            bv[0] = *(const float4*)(W + (size_t)ma0 * CC + ko + k4a0 * 4);
            bv[1] = *(const float4*)(W + (size_t)ma1 * CC + ko + k4a1 * 4);
        }
        #pragma unroll
        for (int kk = 0; kk < 2; kk++) {
            int k0 = kk * 8;
            uint32_t a[4][4], b[4][2];
            #pragma unroll
            for (int i = 0; i < 4; i++) {
                int mb = wm + i * 16 + g;
                a[i][0] = As[s][k0 + l4][mb];
                a[i][1] = As[s][k0 + l4][mb + 8];
                a[i][2] = As[s][k0 + l4 + 4][mb];
                a[i][3] = As[s][k0 + l4 + 4][mb + 8];
            }
            #pragma unroll
            for (int j = 0; j < 4; j++) {
                int nb = wn + j * 8 + g;
                b[j][0] = Bs[s][k0 + l4][nb];
                b[j][1] = Bs[s][k0 + l4 + 4][nb];
            }
            #pragma unroll
            for (int i = 0; i < 4; i++)
                #pragma unroll
                for (int j = 0; j < 4; j++)
                    mma_tf32(acc[i][j], a[i], b[j]);
        }
        if (kb + 1 < NKB) {
            int ns = (kb + 1) & 1;
            As[ns][k4a0 * 4 + 0][ma0] = f2tf32(av[0].x); As[ns][k4a0 * 4 + 1][ma0] = f2tf32(av[0].y);
            As[ns][k4a0 * 4 + 2][ma0] = f2tf32(av[0].z); As[ns][k4a0 * 4 + 3][ma0] = f2tf32(av[0].w);
            As[ns][k4a1 * 4 + 0][ma1] = f2tf32(av[1].x); As[ns][k4a1 * 4 + 1][ma1] = f2tf32(av[1].y);
            As[ns][k4a1 * 4 + 2][ma1] = f2tf32(av[1].z); As[ns][k4a1 * 4 + 3][ma1] = f2tf32(av[1].w);
            Bs[ns][k4a0 * 4 + 0][ma0] = f2tf32(bv[0].x); Bs[ns][k4a0 * 4 + 1][ma0] = f2tf32(bv[0].y);
            Bs[ns][k4a0 * 4 + 2][ma0] = f2tf32(bv[0].z); Bs[ns][k4a0 * 4 + 3][ma0] = f2tf32(bv[0].w);
            Bs[ns][k4a1 * 4 + 0][ma1] = f2tf32(bv[1].x); Bs[ns][k4a1 * 4 + 1][ma1] = f2tf32(bv[1].y);
            Bs[ns][k4a1 * 4 + 2][ma1] = f2tf32(bv[1].z); Bs[ns][k4a1 * 4 + 3][ma1] = f2tf32(bv[1].w);
        }
        __syncthreads();
    }

    // epilogue: bias + relu -> g_H
    #pragma unroll
    for (int i = 0; i < 4; i++) {
        #pragma unroll
        for (int j = 0; j < 4; j++) {
            int col = wn + j * 8 + l4 * 2;
            float b0 = bias[col], b1 = bias[col + 1];
            int r0 = m0 + wm + i * 16 + g;
            size_t base0 = (size_t)r0 * HDIM + col0 + col;
            size_t base1 = (size_t)(r0 + 8) * HDIM + col0 + col;
            g_H[base0 + 0] = fmaxf(acc[i][j][0] + b0, 0.f);
            g_H[base0 + 1] = fmaxf(acc[i][j][1] + b1, 0.f);
            g_H[base1 + 0] = fmaxf(acc[i][j][2] + b0, 0.f);
            g_H[base1 + 1] = fmaxf(acc[i][j][3] + b1, 0.f);
        }
    }
}

// ---------------- layer-2 GEMM (tf32 mma, BN=64) ----------------
// BM=128 BN=64 BK=16, 256 threads (8 warps 4x2), warp tile 32x32
__global__ __launch_bounds__(256) void k_gemm2_mma(int aoff,
                                                   const float* __restrict__ W, const float* __restrict__ bias,
                                                   int outMode) {
    __shared__ uint32_t As[2][16][136];
    __shared__ uint32_t Bs[2][16][72];
    int tid = threadIdx.x;
    int warpid = tid >> 5, lane = tid & 31;
    int g = lane >> 2, l4 = lane & 3;
    int wm = (warpid >> 1) * 32;     // 0,32,64,96
    int wn = (warpid & 1) * 32;      // 0,32
    int m0 = blockIdx.y * 128;
    int col0 = blockIdx.x * 64;

    float acc[2][4][4];
    #pragma unroll
    for (int i = 0; i < 2; i++)
        #pragma unroll
        for (int j = 0; j < 4; j++)
            #pragma unroll
            for (int r = 0; r < 4; r++) acc[i][j][r] = 0.f;

    float4 av[2], bv;
    int f0 = tid, f1 = tid + 256;
    int k4a0 = f0 >> 7, ma0 = f0 & 127;
    int k4a1 = f1 >> 7, ma1 = f1 & 127;
    int k4b = tid >> 6, nb0 = tid & 63;

    {
        av[0] = *(const float4*)(&g_H[(size_t)(m0 + ma0) * HDIM + aoff + k4a0 * 4]);
        av[1] = *(const float4*)(&g_H[(size_t)(m0 + ma1) * HDIM + aoff + k4a1 * 4]);
        bv    = *(const float4*)(W + (size_t)(col0 + nb0) * CC + k4b * 4);
        As[0][k4a0 * 4 + 0][ma0] = f2tf32(av[0].x); As[0][k4a0 * 4 + 1][ma0] = f2tf32(av[0].y);
        As[0][k4a0 * 4 + 2][ma0] = f2tf32(av[0].z); As[0][k4a0 * 4 + 3][ma0] = f2tf32(av[0].w);
        As[0][k4a1 * 4 + 0][ma1] = f2tf32(av[1].x); As[0][k4a1 * 4 + 1][ma1] = f2tf32(av[1].y);
        As[0][k4a1 * 4 + 2][ma1] = f2tf32(av[1].z); As[0][k4a1 * 4 + 3][ma1] = f2tf32(av[1].w);
        Bs[0][k4b * 4 + 0][nb0] = f2tf32(bv.x); Bs[0][k4b * 4 + 1][nb0] = f2tf32(bv.y);
        Bs[0][k4b * 4 + 2][nb0] = f2tf32(bv.z); Bs[0][k4b * 4 + 3][nb0] = f2tf32(bv.w);
    }
    __syncthreads();

    const int NKB = CC / 16;
    for (int kb = 0; kb < NKB; kb++) {
        int s = kb & 1;
        if (kb + 1 < NKB) {
            int ko = (kb + 1) * 16;
            av[0] = *(const float4*)(&g_H[(size_t)(m0 + ma0) * HDIM + aoff + ko + k4a0 * 4]);
            av[1] = *(const float4*)(&g_H[(size_t)(m0 + ma1) * HDIM + aoff + ko + k4a1 * 4]);
            bv    = *(const float4*)(W + (size_t)(col0 + nb0) * CC + ko + k4b * 4);
        }
        #pragma unroll
        for (int kk = 0; kk < 2; kk++) {
            int k0 = kk * 8;
            uint32_t a[2][4], b[4][2];
            #pragma unroll
            for (int i = 0; i < 2; i++) {
                int mb = wm + i * 16 + g;
                a[i][0] = As[s][k0 + l4][mb];
                a[i][1] = As[s][k0 + l4][mb + 8];
                a[i][2] = As[s][k0 + l4 + 4][mb];
                a[i][3] = As[s][k0 + l4 + 4][mb + 8];
            }
            #pragma unroll
            for (int j = 0; j < 4; j++) {
                int nb = wn + j * 8 + g;
                b[j][0] = Bs[s][k0 + l4][nb];
                b[j][1] = Bs[s][k0 + l4 + 4][nb];
            }
            #pragma unroll
            for (int i = 0; i < 2; i++)
                #pragma unroll
                for (int j = 0; j < 4; j++)
                    mma_tf32(acc[i][j], a[i], b[j]);
        }
        if (kb + 1 < NKB) {
            int ns = (kb + 1) & 1;
            As[ns][k4a0 * 4 + 0][ma0] = f2tf32(av[0].x); As[ns][k4a0 * 4 + 1][ma0] = f2tf32(av[0].y);
            As[ns][k4a0 * 4 + 2][ma0] = f2tf32(av[0].z); As[ns][k4a0 * 4 + 3][ma0] = f2tf32(av[0].w);
            As[ns][k4a1 * 4 + 0][ma1] = f2tf32(av[1].x); As[ns][k4a1 * 4 + 1][ma1] = f2tf32(av[1].y);
            As[ns][k4a1 * 4 + 2][ma1] = f2tf32(av[1].z); As[ns][k4a1 * 4 + 3][ma1] = f2tf32(av[1].w);
            Bs[ns][k4b * 4 + 0][nb0] = f2tf32(bv.x); Bs[ns][k4b * 4 + 1][nb0] = f2tf32(bv.y);
            Bs[ns][k4b * 4 + 2][nb0] = f2tf32(bv.z); Bs[ns][k4b * 4 + 3][nb0] = f2tf32(bv.w);
        }
        __syncthreads();
    }

    #pragma unroll
    for (int i = 0; i < 2; i++) {
        #pragma unroll
        for (int j = 0; j < 4; j++) {
            int col = wn + j * 8 + l4 * 2;
            float b0 = bias[col0 + col], b1 = bias[col0 + col + 1];
            int r0 = m0 + wm + i * 16 + g;
            if (outMode == 0) {
                size_t base0 = (size_t)r0 * DD + col0 + col;
                size_t base1 = (size_t)(r0 + 8) * DD + col0 + col;
                g_local[base0 + 0] = acc[i][j][0] + b0;
                g_local[base0 + 1] = acc[i][j][1] + b1;
                g_local[base1 + 0] = acc[i][j][2] + b0;
                g_local[base1 + 1] = acc[i][j][3] + b1;
            } else {
                int b0i = r0 >> 13, n0i = r0 & (NN - 1);
                int b1i = (r0 + 8) >> 13, n1i = (r0 + 8) & (NN - 1);
                g_S[((size_t)b0i * 65 + col0 + col + 0) * NN + n0i] = acc[i][j][0] + b0;
                g_S[((size_t)b0i * 65 + col0 + col + 1) * NN + n0i] = acc[i][j][1] + b1;
                g_S[((size_t)b1i * 65 + col0 + col + 0) * NN + n1i] = acc[i][j][2] + b0;
                g_S[((size_t)b1i * 65 + col0 + col + 1) * NN + n1i] = acc[i][j][3] + b1;
            }
        }
    }
}

// ---------------- dustbin row ----------------
__global__ void k_dust(const float* __restrict__ dust) {
    int i = blockIdx.x * 256 + threadIdx.x;
    int b = i >> 13, n = i & (NN - 1);
    g_S[((size_t)b * 65 + 64) * NN + n] = dust[0];
}

// ---------------- Sinkhorn ----------------
__global__ void k_sink_u() {
    int m = blockIdx.x, b = blockIdx.y, tid = threadIdx.x;
    const float* row = &g_S[((size_t)b * 65 + m) * NN];
    const float* vb = &g_v[b * NN];
    float mx = -1e30f, sm = 0.f;
    for (int n = tid; n < NN; n += 256) {
        float xv = row[n] + vb[n];
        if (xv > mx) { sm = sm * expf(mx - xv) + 1.f; mx = xv; }
        else sm += expf(xv - mx);
    }
    __shared__ float smx[256], ssm[256];
    smx[tid] = mx; ssm[tid] = sm;
    __syncthreads();
    for (int s = 128; s > 0; s >>= 1) {
        if (tid < s) {
            float m1 = smx[tid], s1 = ssm[tid];
            float m2 = smx[tid + s], s2 = ssm[tid + s];
            if (m2 > m1) { s1 = s1 * expf(m1 - m2) + s2; m1 = m2; }
            else s1 += s2 * expf(m2 - m1);
            smx[tid] = m1; ssm[tid] = s1;
        }
        __syncthreads();
    }
    if (tid == 0) {
        float lse = smx[0] + logf(ssm[0]);
        float norm = -logf(8256.0f);
        float loga = (m == 64) ? (norm + logf(8128.0f)) : norm;
        g_u[b * 65 + m] = loga - lse;
    }
}

__global__ void k_sink_v() {
    int b = blockIdx.y;
    int n = blockIdx.x * 256 + threadIdx.x;
    __shared__ float us[65];
    if (threadIdx.x < 65) us[threadIdx.x] = g_u[b * 65 + threadIdx.x];
    __syncthreads();
    const float* col = &g_S[(size_t)b * 65 * NN + n];
    float mx = -1e30f, sm = 0.f;
    for (int m = 0; m < 65; m++) {
        float xv = col[(size_t)m * NN] + us[m];
        if (xv > mx) { sm = sm * expf(mx - xv) + 1.f; mx = xv; }
        else sm += expf(xv - mx);
    }
    g_v[b * NN + n] = -logf(8256.0f) - (mx + logf(sm));
}

__global__ void k_P() {
    int i = blockIdx.x * 256 + threadIdx.x;
    int n = i & (NN - 1);
    int k = (i >> 13) & 63;
    int b = i >> 19;
    float lp = g_S[((size_t)b * 65 + k) * NN + n] + g_u[b * 65 + k] + g_v[b * NN + n] + logf(8256.0f);
    g_P[i] = expf(lp);
}

// ---------------- aggregation ----------------
__global__ __launch_bounds__(256) void k_aggp() {
    int b = blockIdx.y, chunk = blockIdx.x;
    int n0 = chunk * 256;
    int tid = threadIdx.x;
    int tx = tid & 15, ty = tid >> 4;
    int k0 = tx * 4, d0 = ty * 8;
    __shared__ float Ls[32][132];
    __shared__ float Ps[32][68];
    float acc[8][4];
    #pragma unroll
    for (int i = 0; i < 8; i++)
        #pragma unroll
        for (int j = 0; j < 4; j++) acc[i][j] = 0.f;

    for (int c = 0; c < 8; c++) {
        #pragma unroll
        for (int t = 0; t < 4; t++) {
            int f = tid + t * 256;
            int nn = f >> 5; int dq = (f & 31) * 4;
            float4 a = *reinterpret_cast<const float4*>(
                &g_local[((size_t)b * NN + n0 + c * 32 + nn) * DD + dq]);
            Ls[nn][dq + 0] = a.x; Ls[nn][dq + 1] = a.y; Ls[nn][dq + 2] = a.z; Ls[nn][dq + 3] = a.w;
        }
        #pragma unroll
        for (int t = 0; t < 2; t++) {
            int f = tid + t * 256;
            int kk = f >> 3; int nq = (f & 7) * 4;
            float4 pv = *reinterpret_cast<const float4*>(
                &g_P[((size_t)b * KK + kk) * NN + n0 + c * 32 + nq]);
            Ps[nq + 0][kk] = pv.x; Ps[nq + 1][kk] = pv.y; Ps[nq + 2][kk] = pv.z; Ps[nq + 3][kk] = pv.w;
        }
        __syncthreads();
        #pragma unroll
        for (int nn = 0; nn < 32; nn++) {
            float a[8], p[4];
            #pragma unroll
            for (int i = 0; i < 8; i++) a[i] = Ls[nn][d0 + i];
            #pragma unroll
            for (int j = 0; j < 4; j++) p[j] = Ps[nn][k0 + j];
            #pragma unroll
            for (int i = 0; i < 8; i++)
                #pragma unroll
                for (int j = 0; j < 4; j++) acc[i][j] = fmaf(a[i], p[j], acc[i][j]);
        }
        __syncthreads();
    }
    float* out = &g_aggp[((size_t)(b * 32 + chunk)) * DD * KK];
    #pragma unroll
    for (int i = 0; i < 8; i++)
        #pragma unroll
        for (int j = 0; j < 4; j++)
            out[(d0 + i) * KK + k0 + j] = acc[i][j];
}

__global__ void k_aggred() {
    int i = blockIdx.x * 256 + threadIdx.x;
    int b = i >> 13, r = i & 8191;
    float s = 0.f;
    #pragma unroll
    for (int c = 0; c < 32; c++) s += g_aggp[((size_t)(b * 32 + c)) * DD * KK + r];
    g_agg[i] = s;
}

// ---------------- final normalization ----------------
__global__ void k_final(float* __restrict__ out) {
    int b = blockIdx.x, tid = threadIdx.x;
    __shared__ float red[256];
    float gtv = g_gt[b * TOKN + tid];
    red[tid] = gtv * gtv;
    __syncthreads();
    for (int s = 128; s > 0; s >>= 1) { if (tid < s) red[tid] += red[tid + s]; __syncthreads(); }
    float S1 = red[0];
    __syncthreads();
    float s2 = 0.f;
    for (int i = tid; i < DD * KK; i += 256) { float v = g_agg[b * DD * KK + i]; s2 += v * v; }
    red[tid] = s2;
    __syncthreads();
    for (int s = 128; s > 0; s >>= 1) { if (tid < s) red[tid] += red[tid + s]; __syncthreads(); }
    float S2 = red[0];
    float n1 = fmaxf(sqrtf(S1), 1e-12f);
    float n2 = fmaxf(sqrtf(S2), 1e-12f);
    float tot = fmaxf(sqrtf(S1 / (n1 * n1) + S2 / (n2 * n2)), 1e-12f);
    out[(size_t)b * OUTW + tid] = (gtv / n1) / tot;
    for (int i = tid; i < DD * KK; i += 256)
        out[(size_t)b * OUTW + TOKN + i] = (g_agg[b * DD * KK + i] / n2) / tot;
}

// ---------------- launcher ----------------
extern "C" void kernel_launch(void* const* d_in, const int* in_sizes, int n_in,
                              void* d_out, int out_size) {
    const float* x     = (const float*)d_in[0];
    const float* gem_w = (const float*)d_in[1];
    const float* dust  = (const float*)d_in[2];
    const float* tW1 = (const float*)d_in[3];  const float* tb1 = (const float*)d_in[4];
    const float* tW2 = (const float*)d_in[5];  const float* tb2 = (const float*)d_in[6];
    const float* cW1 = (const float*)d_in[7];  const float* cb1 = (const float*)d_in[8];
    const float* cW2 = (const float*)d_in[9];  const float* cb2 = (const float*)d_in[10];
    const float* sW1 = (const float*)d_in[11]; const float* sb1 = (const float*)d_in[12];
    const float* sW2 = (const float*)d_in[13]; const float* sb2 = (const float*)d_in[14];
    float* out = (float*)d_out;

    k_zero_v<<<256, 256>>>();
    k_gem_part<<<dim3(32, 8), 512>>>(x, gem_w);
    k_gem_fin<<<8, 512>>>(gem_w);
    k_tok1<<<512, 256>>>(tW1, tb1);
    k_tok2<<<256, 256>>>(tW2, tb2);

    k_gemm1_mma<<<dim3(8, 512), 256>>>(x, cW1, cb1, sW1, sb1);
    k_dust<<<256, 256>>>(dust);
    k_gemm2_mma<<<dim3(2, 512), 256>>>(0, cW2, cb2, 0);    // local
    k_gemm2_mma<<<dim3(1, 512), 256>>>(512, sW2, sb2, 1);  // scores -> S^T

    for (int it = 0; it < 3; it++) {
        k_sink_u<<<dim3(65, 8), 256>>>();
        k_sink_v<<<dim3(32, 8), 256>>>();
    }
    k_P<<<16384, 256>>>();

    k_aggp<<<dim3(32, 8), 256>>>();
    k_aggred<<<256, 256>>>();
    k_final<<<8, 256>>>(out);
}

// round 5
// speedup vs baseline: 3.1690x; 1.7970x over previous
#include <cuda_runtime.h>
#include <math.h>
#include <stdint.h>

// ---------------- problem constants ----------------
#define BB 8
#define NN 8192
#define CC 512
#define KK 64
#define DD 128
#define TOKN 256
#define MTOT (BB*NN)          // 65536
#define HDIM 1024
#define OUTW (TOKN + DD*KK)   // 8448

// ---------------- scratch (device globals) ----------------
__device__ float g_H[(size_t)MTOT * HDIM];          // layer-1 activations
__device__ float g_E[(size_t)BB * 65 * NN];         // exp(scores) [b,65,n]
__device__ float g_local[(size_t)MTOT * DD];
__device__ float g_eu[BB * 65];
__device__ float g_ev[BB * NN];
__device__ float g_gp[BB * 32 * CC];
__device__ float g_g[BB * CC];
__device__ float g_h1[BB * 512];
__device__ float g_gt[BB * TOKN];
__device__ float g_aggp[(size_t)BB * 32 * DD * KK];
__device__ float g_agg[BB * DD * KK];
__device__ float g_W1r[1024 * 512];                 // [cW1;sW1] tf32-rounded
__device__ float g_W2r[192 * 512];                  // [cW2;sW2] tf32-rounded
__device__ float g_b1r[1024];
__device__ float g_b2r[192];

// ---------------- helpers ----------------
__device__ __forceinline__ float compute_p(float w) {
    float sp = (w > 20.f) ? w : log1pf(expf(w));
    return fminf(sp + 1e-3f, 10.0f);
}
__device__ __forceinline__ float tf32r(float x) {
    uint32_t r;
    asm("cvt.rna.tf32.f32 %0, %1;" : "=r"(r) : "f"(x));
    return __uint_as_float(r);
}
__device__ __forceinline__ uint32_t smem_u32(const void* p) {
    uint32_t a;
    asm("{ .reg .u64 t; cvta.to.shared.u64 t, %1; cvt.u32.u64 %0, t; }" : "=r"(a) : "l"(p));
    return a;
}
__device__ __forceinline__ void cp16(uint32_t dst, const void* src) {
    asm volatile("cp.async.cg.shared.global [%0], [%1], 16;" :: "r"(dst), "l"(src));
}
__device__ __forceinline__ void cp_commit() {
    asm volatile("cp.async.commit_group;" ::: "memory");
}
template<int N> __device__ __forceinline__ void cp_wait() {
    asm volatile("cp.async.wait_group %0;" :: "n"(N) : "memory");
}
__device__ __forceinline__ void mma_tf32(float* d, const uint32_t* a, const uint32_t* b) {
    asm volatile(
        "mma.sync.aligned.m16n8k8.row.col.f32.tf32.tf32.f32 "
        "{%0,%1,%2,%3}, {%4,%5,%6,%7}, {%8,%9}, {%0,%1,%2,%3};\n"
        : "+f"(d[0]), "+f"(d[1]), "+f"(d[2]), "+f"(d[3])
        : "r"(a[0]), "r"(a[1]), "r"(a[2]), "r"(a[3]), "r"(b[0]), "r"(b[1]));
}

// ---------------- weight prep: round to tf32, concat ----------------
__global__ void k_prep(const float* __restrict__ cW1, const float* __restrict__ cb1,
                       const float* __restrict__ sW1, const float* __restrict__ sb1,
                       const float* __restrict__ cW2, const float* __restrict__ cb2,
                       const float* __restrict__ sW2, const float* __restrict__ sb2) {
    int i = blockIdx.x * 256 + threadIdx.x;   // 2432*256 = 622592
    if (i < 1024 * 512) {
        g_W1r[i] = tf32r(i < 512 * 512 ? cW1[i] : sW1[i - 512 * 512]);
    } else {
        int j = i - 1024 * 512;               // < 98304
        if (j < 128 * 512) g_W2r[j] = tf32r(cW2[j]);
        else               g_W2r[j] = tf32r(sW2[j - 128 * 512]);
    }
    if (i < 1024) g_b1r[i] = (i < 512) ? cb1[i] : sb1[i - 512];
    else if (i < 1024 + 192) { int j = i - 1024; g_b2r[j] = (j < 128) ? cb2[j] : sb2[j - 128]; }
}

__global__ void k_initev() {
    int i = blockIdx.x * 256 + threadIdx.x;   // 65536
    g_ev[i] = 1.f;
}

// ---------------- GeM pooling ----------------
__global__ void k_gem_part(const float* __restrict__ x, const float* __restrict__ gem_w) {
    int b = blockIdx.y, part = blockIdx.x, c = threadIdx.x;
    float p = compute_p(gem_w[0]);
    bool cube = fabsf(p - 3.0f) < 1e-5f;
    const float* xp = x + ((size_t)b * NN + part * 256) * CC + c;
    float s = 0.f;
    if (cube) {
        #pragma unroll 4
        for (int n = 0; n < 256; n++) {
            float v = fmaxf(xp[(size_t)n * CC], 1e-6f);
            s += v * v * v;
        }
    } else {
        for (int n = 0; n < 256; n++) {
            float v = fmaxf(xp[(size_t)n * CC], 1e-6f);
            s += __powf(v, p);
        }
    }
    g_gp[(b * 32 + part) * CC + c] = s;
}

__global__ void k_gem_fin(const float* __restrict__ gem_w) {
    int b = blockIdx.x, c = threadIdx.x;
    float s = 0.f;
    #pragma unroll
    for (int i = 0; i < 32; i++) s += g_gp[(b * 32 + i) * CC + c];
    float p = compute_p(gem_w[0]);
    float mean = s * (1.0f / (float)NN);
    float g = powf(mean, 1.0f / p);
    if (!isfinite(g)) g = 0.f;
    g_g[b * CC + c] = g;
}

// ---------------- token MLP: warp per output ----------------
__global__ void k_tok1(const float* __restrict__ tW1, const float* __restrict__ tb1) {
    int warp = blockIdx.x * 8 + (threadIdx.x >> 5);
    int lane = threadIdx.x & 31;
    int b = warp >> 9, t = warp & 511;
    const float* g = &g_g[b * CC];
    const float* w = tW1 + (size_t)t * CC;
    float s = 0.f;
    #pragma unroll
    for (int c = lane; c < CC; c += 32) s = fmaf(g[c], w[c], s);
    #pragma unroll
    for (int o = 16; o > 0; o >>= 1) s += __shfl_xor_sync(0xffffffffu, s, o);
    if (lane == 0) g_h1[b * 512 + t] = fmaxf(s + tb1[t], 0.f);
}

__global__ void k_tok2(const float* __restrict__ tW2, const float* __restrict__ tb2) {
    int warp = blockIdx.x * 8 + (threadIdx.x >> 5);
    int lane = threadIdx.x & 31;
    int b = warp >> 8, t = warp & 255;
    const float* h = &g_h1[b * 512];
    const float* w = tW2 + (size_t)t * 512;
    float s = 0.f;
    #pragma unroll
    for (int c = lane; c < 512; c += 32) s = fmaf(h[c], w[c], s);
    #pragma unroll
    for (int o = 16; o > 0; o >>= 1) s += __shfl_xor_sync(0xffffffffu, s, o);
    if (lane == 0) g_gt[b * TOKN + t] = s + tb2[t];
}

// ================ tf32 mma.sync GEMM with cp.async pipeline ================
// BM=128, BN template, BK=16, 4 stages, 256 threads, 2 CTAs/SM.
// smem rows padded to 20 floats (16 data + 4) -> conflict-free fragment loads.
// MODE 0: H = relu(X @ W1^T + b1)           (BN=128, A=x, lda=512)
// MODE 1: local = H[:, :512] @ cW2^T + b    (BN=64)
// MODE 2: E = exp(H[:, 512:] @ sW2^T + b)   (BN=64, transposed store)
template<int BN, int MODE>
__global__ __launch_bounds__(256, 2) void k_mm(const float* __restrict__ Aopt) {
    constexpr int STAGES = 4;
    constexpr int NKB = 32;                    // 512 / 16
    constexpr int ROWS = 128 + BN;             // A rows + B rows per stage
    constexpr int STRIDE = 20;                 // floats per row (16 + 4 pad)
    constexpr int NWN = BN / 32;               // warps along N: 4 or 2
    constexpr int NWM = 8 / NWN;               // warps along M: 2 or 4
    constexpr int MI = (128 / NWM) / 16;       // m16 subtiles per warp: 4 or 2

    extern __shared__ __align__(16) float smem[];   // [STAGES][ROWS][STRIDE]
    uint32_t sbase = smem_u32(smem);

    int tid = threadIdx.x;
    int warpid = tid >> 5, lane = tid & 31;
    int g = lane >> 2, l4 = lane & 3;
    int wm = (warpid / NWN) * (128 / NWM);
    int wn = (warpid % NWN) * 32;
    int m0 = blockIdx.y * 128;
    int col0 = blockIdx.x * BN;

    const float* Ap; int lda; const float* Bw; const float* bias;
    if (MODE == 0)      { Ap = Aopt;       lda = 512;  Bw = g_W1r;             bias = g_b1r; }
    else if (MODE == 1) { Ap = g_H;        lda = 1024; Bw = g_W2r;             bias = g_b2r; }
    else                { Ap = g_H + 512;  lda = 1024; Bw = g_W2r + 128 * 512; bias = g_b2r + 128; }

    float acc[MI][4][4];
    #pragma unroll
    for (int i = 0; i < MI; i++)
        #pragma unroll
        for (int j = 0; j < 4; j++)
            #pragma unroll
            for (int r = 0; r < 4; r++) acc[i][j][r] = 0.f;

    // ---- stage loader: BK=16 cols [kb*16, kb*16+16) ----
    auto load_stage = [&](int kb, int st) {
        uint32_t base = sbase + (uint32_t)st * ROWS * STRIDE * 4;
        int ko = kb * 16;
        constexpr int CHUNKS = ROWS * 4;       // 16B chunks
        #pragma unroll
        for (int t = 0; t < CHUNKS / 256; t++) {
            int c = tid + t * 256;
            int row = c >> 2, q = c & 3;
            const float* src = (row < 128)
                ? (Ap + (size_t)(m0 + row) * lda + ko + q * 4)
                : (Bw + (size_t)(col0 + row - 128) * 512 + ko + q * 4);
            cp16(base + (uint32_t)(row * STRIDE + q * 4) * 4, src);
        }
    };

    // prologue: stages 0..2
    #pragma unroll
    for (int s = 0; s < STAGES - 1; s++) { load_stage(s, s); cp_commit(); }

    for (int kb = 0; kb < NKB; kb++) {
        cp_wait<STAGES - 2>();
        __syncthreads();
        if (kb + STAGES - 1 < NKB) load_stage(kb + STAGES - 1, (kb + STAGES - 1) % STAGES);
        cp_commit();

        const uint32_t* Ash = (const uint32_t*)(smem + (size_t)(kb % STAGES) * ROWS * STRIDE);
        const uint32_t* Bsh = Ash + 128 * STRIDE;
        #pragma unroll
        for (int kk = 0; kk < 2; kk++) {
            int k0 = kk * 8;
            uint32_t a[MI][4], b[4][2];
            #pragma unroll
            for (int i = 0; i < MI; i++) {
                int mb = wm + i * 16 + g;
                a[i][0] = Ash[mb * STRIDE + k0 + l4];
                a[i][1] = Ash[(mb + 8) * STRIDE + k0 + l4];
                a[i][2] = Ash[mb * STRIDE + k0 + l4 + 4];
                a[i][3] = Ash[(mb + 8) * STRIDE + k0 + l4 + 4];
            }
            #pragma unroll
            for (int j = 0; j < 4; j++) {
                int nb = wn + j * 8 + g;
                b[j][0] = Bsh[nb * STRIDE + k0 + l4];
                b[j][1] = Bsh[nb * STRIDE + k0 + l4 + 4];
            }
            #pragma unroll
            for (int i = 0; i < MI; i++)
                #pragma unroll
                for (int j = 0; j < 4; j++)
                    mma_tf32(acc[i][j], a[i], b[j]);
        }
    }

    // ---- epilogue ----
    #pragma unroll
    for (int i = 0; i < MI; i++) {
        #pragma unroll
        for (int j = 0; j < 4; j++) {
            int col = wn + j * 8 + l4 * 2;
            float b0 = bias[col0 + col], b1 = bias[col0 + col + 1];
            int r0 = m0 + wm + i * 16 + g;
            if (MODE == 0) {
                size_t base0 = (size_t)r0 * HDIM + col0 + col;
                size_t base1 = (size_t)(r0 + 8) * HDIM + col0 + col;
                g_H[base0 + 0] = fmaxf(acc[i][j][0] + b0, 0.f);
                g_H[base0 + 1] = fmaxf(acc[i][j][1] + b1, 0.f);
                g_H[base1 + 0] = fmaxf(acc[i][j][2] + b0, 0.f);
                g_H[base1 + 1] = fmaxf(acc[i][j][3] + b1, 0.f);
            } else if (MODE == 1) {
                size_t base0 = (size_t)r0 * DD + col0 + col;
                size_t base1 = (size_t)(r0 + 8) * DD + col0 + col;
                g_local[base0 + 0] = acc[i][j][0] + b0;
                g_local[base0 + 1] = acc[i][j][1] + b1;
                g_local[base1 + 0] = acc[i][j][2] + b0;
                g_local[base1 + 1] = acc[i][j][3] + b1;
            } else {
                int b0i = r0 >> 13, n0i = r0 & (NN - 1);
                int b1i = (r0 + 8) >> 13, n1i = (r0 + 8) & (NN - 1);
                int kc = col0 + col;
                g_E[((size_t)b0i * 65 + kc + 0) * NN + n0i] = expf(acc[i][j][0] + b0);
                g_E[((size_t)b0i * 65 + kc + 1) * NN + n0i] = expf(acc[i][j][1] + b1);
                g_E[((size_t)b1i * 65 + kc + 0) * NN + n1i] = expf(acc[i][j][2] + b0);
                g_E[((size_t)b1i * 65 + kc + 1) * NN + n1i] = expf(acc[i][j][3] + b1);
            }
        }
    }
}

// ---------------- dust row of E ----------------
__global__ void k_dustE(const float* __restrict__ dust) {
    int i = blockIdx.x * 256 + threadIdx.x;   // 65536
    int b = i >> 13, n = i & (NN - 1);
    g_E[((size_t)b * 65 + 64) * NN + n] = expf(dust[0]);
}

// ---------------- linear-domain Sinkhorn ----------------
__global__ void k_row() {                      // grid (65, 8), 256 thr
    int m = blockIdx.x, b = blockIdx.y, tid = threadIdx.x;
    const float* row = &g_E[((size_t)b * 65 + m) * NN];
    const float* ev = &g_ev[b * NN];
    float s = 0.f;
    for (int n = tid; n < NN; n += 256) s = fmaf(row[n], ev[n], s);
    __shared__ float red[256];
    red[tid] = s;
    __syncthreads();
    #pragma unroll
    for (int o = 128; o > 0; o >>= 1) {
        if (tid < o) red[tid] += red[tid + o];
        __syncthreads();
    }
    if (tid == 0) {
        float a = (m == 64) ? (8128.f / 8256.f) : (1.f / 8256.f);
        g_eu[b * 65 + m] = a / red[0];
    }
}

__global__ void k_col() {                      // grid (32, 8), 256 thr
    int b = blockIdx.y;
    int n = blockIdx.x * 256 + threadIdx.x;
    __shared__ float us[65];
    if (threadIdx.x < 65) us[threadIdx.x] = g_eu[b * 65 + threadIdx.x];
    __syncthreads();
    const float* col = &g_E[(size_t)b * 65 * NN + n];
    float s = 0.f;
    #pragma unroll
    for (int m = 0; m < 65; m++) s = fmaf(col[(size_t)m * NN], us[m], s);
    g_ev[b * NN + n] = (1.f / 8256.f) / s;
}

// ---------------- aggregation: agg[b,d,k] = sum_n local[b,n,d]*P[b,k,n] ----------------
// P folded on the fly: P = E * eu[k] * ev[n] * 8256
__global__ __launch_bounds__(256) void k_aggp() {
    int b = blockIdx.y, chunk = blockIdx.x;
    int n0 = chunk * 256;
    int tid = threadIdx.x;
    int tx = tid & 15, ty = tid >> 4;
    int k0 = tx * 4, d0 = ty * 8;
    __shared__ float Ls[32][132];
    __shared__ float Ps[32][68];
    float acc[8][4];
    #pragma unroll
    for (int i = 0; i < 8; i++)
        #pragma unroll
        for (int j = 0; j < 4; j++) acc[i][j] = 0.f;

    for (int c = 0; c < 8; c++) {
        #pragma unroll
        for (int t = 0; t < 4; t++) {
            int f = tid + t * 256;
            int nn = f >> 5; int dq = (f & 31) * 4;
            float4 a = *reinterpret_cast<const float4*>(
                &g_local[((size_t)b * NN + n0 + c * 32 + nn) * DD + dq]);
            Ls[nn][dq + 0] = a.x; Ls[nn][dq + 1] = a.y; Ls[nn][dq + 2] = a.z; Ls[nn][dq + 3] = a.w;
        }
        #pragma unroll
        for (int t = 0; t < 2; t++) {
            int f = tid + t * 256;
            int kk = f >> 3; int nq = (f & 7) * 4;
            int nb = n0 + c * 32 + nq;
            float euk = g_eu[b * 65 + kk] * 8256.f;
            float4 e4 = *reinterpret_cast<const float4*>(&g_E[((size_t)b * 65 + kk) * NN + nb]);
            float4 v4 = *reinterpret_cast<const float4*>(&g_ev[b * NN + nb]);
            Ps[nq + 0][kk] = e4.x * v4.x * euk;
            Ps[nq + 1][kk] = e4.y * v4.y * euk;
            Ps[nq + 2][kk] = e4.z * v4.z * euk;
            Ps[nq + 3][kk] = e4.w * v4.w * euk;
        }
        __syncthreads();
        #pragma unroll
        for (int nn = 0; nn < 32; nn++) {
            float a[8], p[4];
            #pragma unroll
            for (int i = 0; i < 8; i++) a[i] = Ls[nn][d0 + i];
            #pragma unroll
            for (int j = 0; j < 4; j++) p[j] = Ps[nn][k0 + j];
            #pragma unroll
            for (int i = 0; i < 8; i++)
                #pragma unroll
                for (int j = 0; j < 4; j++) acc[i][j] = fmaf(a[i], p[j], acc[i][j]);
        }
        __syncthreads();
    }
    float* out = &g_aggp[((size_t)(b * 32 + chunk)) * DD * KK];
    #pragma unroll
    for (int i = 0; i < 8; i++)
        #pragma unroll
        for (int j = 0; j < 4; j++)
            out[(d0 + i) * KK + k0 + j] = acc[i][j];
}

__global__ void k_aggred() {
    int i = blockIdx.x * 256 + threadIdx.x;
    int b = i >> 13, r = i & 8191;
    float s = 0.f;
    #pragma unroll
    for (int c = 0; c < 32; c++) s += g_aggp[((size_t)(b * 32 + c)) * DD * KK + r];
    g_agg[i] = s;
}

// ---------------- final normalization ----------------
__global__ void k_final(float* __restrict__ out) {
    int b = blockIdx.x, tid = threadIdx.x;
    __shared__ float red[256];
    float gtv = g_gt[b * TOKN + tid];
    red[tid] = gtv * gtv;
    __syncthreads();
    for (int s = 128; s > 0; s >>= 1) { if (tid < s) red[tid] += red[tid + s]; __syncthreads(); }
    float S1 = red[0];
    __syncthreads();
    float s2 = 0.f;
    for (int i = tid; i < DD * KK; i += 256) { float v = g_agg[b * DD * KK + i]; s2 += v * v; }
    red[tid] = s2;
    __syncthreads();
    for (int s = 128; s > 0; s >>= 1) { if (tid < s) red[tid] += red[tid + s]; __syncthreads(); }
    float S2 = red[0];
    float n1 = fmaxf(sqrtf(S1), 1e-12f);
    float n2 = fmaxf(sqrtf(S2), 1e-12f);
    float tot = fmaxf(sqrtf(S1 / (n1 * n1) + S2 / (n2 * n2)), 1e-12f);
    out[(size_t)b * OUTW + tid] = (gtv / n1) / tot;
    for (int i = tid; i < DD * KK; i += 256)
        out[(size_t)b * OUTW + TOKN + i] = (g_agg[b * DD * KK + i] / n2) / tot;
}

// ---------------- launcher ----------------
extern "C" void kernel_launch(void* const* d_in, const int* in_sizes, int n_in,
                              void* d_out, int out_size) {
    const float* x     = (const float*)d_in[0];
    const float* gem_w = (const float*)d_in[1];
    const float* dust  = (const float*)d_in[2];
    const float* tW1 = (const float*)d_in[3];  const float* tb1 = (const float*)d_in[4];
    const float* tW2 = (const float*)d_in[5];  const float* tb2 = (const float*)d_in[6];
    const float* cW1 = (const float*)d_in[7];  const float* cb1 = (const float*)d_in[8];
    const float* cW2 = (const float*)d_in[9];  const float* cb2 = (const float*)d_in[10];
    const float* sW1 = (const float*)d_in[11]; const float* sb1 = (const float*)d_in[12];
    const float* sW2 = (const float*)d_in[13]; const float* sb2 = (const float*)d_in[14];
    float* out = (float*)d_out;

    const int SM1 = 4 * (128 + 128) * 20 * 4;   // 81920 B (BN=128)
    const int SM2 = 4 * (128 + 64) * 20 * 4;    // 61440 B (BN=64)
    cudaFuncSetAttribute(k_mm<128, 0>, cudaFuncAttributeMaxDynamicSharedMemorySize, SM1);
    cudaFuncSetAttribute(k_mm<64, 1>,  cudaFuncAttributeMaxDynamicSharedMemorySize, SM2);
    cudaFuncSetAttribute(k_mm<64, 2>,  cudaFuncAttributeMaxDynamicSharedMemorySize, SM2);

    k_prep<<<2432, 256>>>(cW1, cb1, sW1, sb1, cW2, cb2, sW2, sb2);
    k_initev<<<256, 256>>>();
    k_gem_part<<<dim3(32, 8), 512>>>(x, gem_w);
    k_gem_fin<<<8, 512>>>(gem_w);
    k_tok1<<<512, 256>>>(tW1, tb1);
    k_tok2<<<256, 256>>>(tW2, tb2);

    k_mm<128, 0><<<dim3(8, 512), 256, SM1>>>(x);        // H = relu(X @ W1^T + b1)
    k_mm<64, 1><<<dim3(2, 512), 256, SM2>>>(nullptr);   // local
    k_mm<64, 2><<<dim3(1, 512), 256, SM2>>>(nullptr);   // E = exp(scores)
    k_dustE<<<256, 256>>>(dust);

    for (int it = 0; it < 3; it++) {
        k_row<<<dim3(65, 8), 256>>>();
        k_col<<<dim3(32, 8), 256>>>();
    }

    k_aggp<<<dim3(32, 8), 256>>>();
    k_aggred<<<256, 256>>>();
    k_final<<<8, 256>>>(out);
}

// round 6
// speedup vs baseline: 5.2239x; 1.6484x over previous
#include <cuda_runtime.h>
#include <cuda_fp16.h>
#include <math.h>
#include <stdint.h>

// ---------------- problem constants ----------------
#define BB 8
#define NN 8192
#define CC 512
#define KK 64
#define DD 128
#define TOKN 256
#define MTOT (BB*NN)          // 65536
#define HDIM 1024
#define OUTW (TOKN + DD*KK)   // 8448

// ---------------- scratch (device globals) ----------------
__device__ __half g_Xh[(size_t)MTOT * CC];          // fp16 copy of x
__device__ __half g_Hh[(size_t)MTOT * HDIM];        // layer-1 activations (fp16)
__device__ float g_E[(size_t)BB * 65 * NN];         // exp(scores) [b,65,n]
__device__ float g_local[(size_t)MTOT * DD];
__device__ float g_eu[BB * 65];
__device__ float g_ev[BB * NN];
__device__ float g_gp[BB * 32 * CC];
__device__ float g_g[BB * CC];
__device__ float g_h1[BB * 512];
__device__ float g_gt[BB * TOKN];
__device__ float g_aggp[(size_t)BB * 32 * DD * KK];
__device__ float g_agg[BB * DD * KK];
__device__ __half g_W1h[1024 * 512];                // [cW1;sW1] fp16
__device__ __half g_W2h[192 * 512];                 // [cW2;sW2] fp16
__device__ float g_b1r[1024];
__device__ float g_b2r[192];

// ---------------- helpers ----------------
__device__ __forceinline__ float compute_p(float w) {
    float sp = (w > 20.f) ? w : log1pf(expf(w));
    return fminf(sp + 1e-3f, 10.0f);
}
__device__ __forceinline__ uint32_t smem_u32(const void* p) {
    uint32_t a;
    asm("{ .reg .u64 t; cvta.to.shared.u64 t, %1; cvt.u32.u64 %0, t; }" : "=r"(a) : "l"(p));
    return a;
}
__device__ __forceinline__ void cp16(uint32_t dst, const void* src) {
    asm volatile("cp.async.cg.shared.global [%0], [%1], 16;" :: "r"(dst), "l"(src));
}
__device__ __forceinline__ void cp_commit() {
    asm volatile("cp.async.commit_group;" ::: "memory");
}
template<int N> __device__ __forceinline__ void cp_wait() {
    asm volatile("cp.async.wait_group %0;" :: "n"(N) : "memory");
}
// fp16 mma: D(f32) += A(f16) * B(f16), m16n8k16, row.col
__device__ __forceinline__ void mma_f16(float* d, const uint32_t* a, const uint32_t* b) {
    asm volatile(
        "mma.sync.aligned.m16n8k16.row.col.f32.f16.f16.f32 "
        "{%0,%1,%2,%3}, {%4,%5,%6,%7}, {%8,%9}, {%0,%1,%2,%3};\n"
        : "+f"(d[0]), "+f"(d[1]), "+f"(d[2]), "+f"(d[3])
        : "r"(a[0]), "r"(a[1]), "r"(a[2]), "r"(a[3]), "r"(b[0]), "r"(b[1]));
}

// ---------------- weight prep: convert to fp16, concat ----------------
__global__ void k_prep(const float* __restrict__ cW1, const float* __restrict__ cb1,
                       const float* __restrict__ sW1, const float* __restrict__ sb1,
                       const float* __restrict__ cW2, const float* __restrict__ cb2,
                       const float* __restrict__ sW2, const float* __restrict__ sb2) {
    int i = blockIdx.x * 256 + threadIdx.x;   // 2432*256 = 622592
    if (i < 1024 * 512) {
        g_W1h[i] = __float2half_rn(i < 512 * 512 ? cW1[i] : sW1[i - 512 * 512]);
    } else {
        int j = i - 1024 * 512;               // < 98304
        if (j < 128 * 512) g_W2h[j] = __float2half_rn(cW2[j]);
        else               g_W2h[j] = __float2half_rn(sW2[j - 128 * 512]);
    }
    if (i < 1024) g_b1r[i] = (i < 512) ? cb1[i] : sb1[i - 512];
    else if (i < 1024 + 192) { int j = i - 1024; g_b2r[j] = (j < 128) ? cb2[j] : sb2[j - 128]; }
}

__global__ void k_initev() {
    int i = blockIdx.x * 256 + threadIdx.x;   // 65536
    g_ev[i] = 1.f;
}

// ---------------- GeM pooling (+ fp16 conversion of x, fused) ----------------
__global__ void k_gem_part(const float* __restrict__ x, const float* __restrict__ gem_w) {
    int b = blockIdx.y, part = blockIdx.x, c = threadIdx.x;
    float p = compute_p(gem_w[0]);
    bool cube = fabsf(p - 3.0f) < 1e-5f;
    size_t base = ((size_t)b * NN + part * 256) * CC + c;
    const float* xp = x + base;
    __half* xh = g_Xh + base;
    float s = 0.f;
    if (cube) {
        #pragma unroll 4
        for (int n = 0; n < 256; n++) {
            float xv = xp[(size_t)n * CC];
            xh[(size_t)n * CC] = __float2half_rn(xv);
            float v = fmaxf(xv, 1e-6f);
            s += v * v * v;
        }
    } else {
        for (int n = 0; n < 256; n++) {
            float xv = xp[(size_t)n * CC];
            xh[(size_t)n * CC] = __float2half_rn(xv);
            float v = fmaxf(xv, 1e-6f);
            s += __powf(v, p);
        }
    }
    g_gp[(b * 32 + part) * CC + c] = s;
}

__global__ void k_gem_fin(const float* __restrict__ gem_w) {
    int b = blockIdx.x, c = threadIdx.x;
    float s = 0.f;
    #pragma unroll
    for (int i = 0; i < 32; i++) s += g_gp[(b * 32 + i) * CC + c];
    float p = compute_p(gem_w[0]);
    float mean = s * (1.0f / (float)NN);
    float g = powf(mean, 1.0f / p);
    if (!isfinite(g)) g = 0.f;
    g_g[b * CC + c] = g;
}

// ---------------- token MLP: warp per output ----------------
__global__ void k_tok1(const float* __restrict__ tW1, const float* __restrict__ tb1) {
    int warp = blockIdx.x * 8 + (threadIdx.x >> 5);
    int lane = threadIdx.x & 31;
    int b = warp >> 9, t = warp & 511;
    const float* g = &g_g[b * CC];
    const float* w = tW1 + (size_t)t * CC;
    float s = 0.f;
    #pragma unroll
    for (int c = lane; c < CC; c += 32) s = fmaf(g[c], w[c], s);
    #pragma unroll
    for (int o = 16; o > 0; o >>= 1) s += __shfl_xor_sync(0xffffffffu, s, o);
    if (lane == 0) g_h1[b * 512 + t] = fmaxf(s + tb1[t], 0.f);
}

__global__ void k_tok2(const float* __restrict__ tW2, const float* __restrict__ tb2) {
    int warp = blockIdx.x * 8 + (threadIdx.x >> 5);
    int lane = threadIdx.x & 31;
    int b = warp >> 8, t = warp & 255;
    const float* h = &g_h1[b * 512];
    const float* w = tW2 + (size_t)t * 512;
    float s = 0.f;
    #pragma unroll
    for (int c = lane; c < 512; c += 32) s = fmaf(h[c], w[c], s);
    #pragma unroll
    for (int o = 16; o > 0; o >>= 1) s += __shfl_xor_sync(0xffffffffu, s, o);
    if (lane == 0) g_gt[b * TOKN + t] = s + tb2[t];
}

// ================ fp16 mma.sync GEMM with cp.async pipeline ================
// BM=128, BN template, BK=32 halfs, 4 stages, 256 threads, 2 CTAs/SM.
// smem rows: 32 data halfs + 8 pad = 40 halfs (80 B) -> conflict-free frag loads.
// MODE 0: Hh = relu_h(Xh @ W1h^T + b1)       (BN=128, A=g_Xh, lda=512)
// MODE 1: local = Hh[:, :512] @ cW2h^T + b   (BN=128)
// MODE 2: E = exp(Hh[:, 512:] @ sW2h^T + b)  (BN=64, transposed store)
template<int BN, int MODE>
__global__ __launch_bounds__(256, 2) void k_mm() {
    constexpr int STAGES = 4;
    constexpr int NKB = 16;                    // 512 / 32
    constexpr int ROWS = 128 + BN;
    constexpr int STRIDE_H = 40;               // halfs per row (32 + 8 pad)
    constexpr int STRIDE_U = 20;               // u32 per row
    constexpr int NWN = BN / 32;               // warps along N
    constexpr int NWM = 8 / NWN;
    constexpr int MI = (128 / NWM) / 16;

    extern __shared__ __align__(16) __half smem[];   // [STAGES][ROWS][STRIDE_H]
    uint32_t sbase = smem_u32(smem);

    int tid = threadIdx.x;
    int warpid = tid >> 5, lane = tid & 31;
    int g = lane >> 2, l4 = lane & 3;
    int wm = (warpid / NWN) * (128 / NWM);
    int wn = (warpid % NWN) * 32;
    int m0 = blockIdx.y * 128;
    int col0 = blockIdx.x * BN;

    const __half* Ap; int lda; const __half* Bw; const float* bias;
    if (MODE == 0)      { Ap = g_Xh;        lda = 512;  Bw = g_W1h;             bias = g_b1r; }
    else if (MODE == 1) { Ap = g_Hh;        lda = 1024; Bw = g_W2h;             bias = g_b2r; }
    else                { Ap = g_Hh + 512;  lda = 1024; Bw = g_W2h + 128 * 512; bias = g_b2r + 128; }

    float acc[MI][4][4];
    #pragma unroll
    for (int i = 0; i < MI; i++)
        #pragma unroll
        for (int j = 0; j < 4; j++)
            #pragma unroll
            for (int r = 0; r < 4; r++) acc[i][j][r] = 0.f;

    // ---- stage loader: 32 K-halfs [kb*32, kb*32+32) ----
    auto load_stage = [&](int kb, int st) {
        uint32_t base = sbase + (uint32_t)st * ROWS * STRIDE_H * 2;
        int ko = kb * 32;
        constexpr int CHUNKS = ROWS * 4;       // 16B chunks (8 halfs each)
        #pragma unroll
        for (int t = 0; t < CHUNKS / 256; t++) {
            int c = tid + t * 256;
            int row = c >> 2, q = c & 3;
            const __half* src = (row < 128)
                ? (Ap + (size_t)(m0 + row) * lda + ko + q * 8)
                : (Bw + (size_t)(col0 + row - 128) * 512 + ko + q * 8);
            cp16(base + (uint32_t)(row * STRIDE_H + q * 8) * 2, src);
        }
    };

    #pragma unroll
    for (int s = 0; s < STAGES - 1; s++) { load_stage(s, s); cp_commit(); }

    for (int kb = 0; kb < NKB; kb++) {
        cp_wait<STAGES - 2>();
        __syncthreads();
        if (kb + STAGES - 1 < NKB) load_stage(kb + STAGES - 1, (kb + STAGES - 1) % STAGES);
        cp_commit();

        const uint32_t* Ash = (const uint32_t*)(smem + (size_t)(kb % STAGES) * ROWS * STRIDE_H);
        const uint32_t* Bsh = Ash + 128 * STRIDE_U;
        #pragma unroll
        for (int kk = 0; kk < 2; kk++) {
            int k0 = kk * 8;                   // in u32 units (16 halfs)
            uint32_t a[MI][4], b[4][2];
            #pragma unroll
            for (int i = 0; i < MI; i++) {
                int mb = wm + i * 16 + g;
                a[i][0] = Ash[mb * STRIDE_U + k0 + l4];
                a[i][1] = Ash[(mb + 8) * STRIDE_U + k0 + l4];
                a[i][2] = Ash[mb * STRIDE_U + k0 + l4 + 4];
                a[i][3] = Ash[(mb + 8) * STRIDE_U + k0 + l4 + 4];
            }
            #pragma unroll
            for (int j = 0; j < 4; j++) {
                int nb = wn + j * 8 + g;
                b[j][0] = Bsh[nb * STRIDE_U + k0 + l4];
                b[j][1] = Bsh[nb * STRIDE_U + k0 + l4 + 4];
            }
            #pragma unroll
            for (int i = 0; i < MI; i++)
                #pragma unroll
                for (int j = 0; j < 4; j++)
                    mma_f16(acc[i][j], a[i], b[j]);
        }
    }

    // ---- epilogue ----
    #pragma unroll
    for (int i = 0; i < MI; i++) {
        #pragma unroll
        for (int j = 0; j < 4; j++) {
            int col = wn + j * 8 + l4 * 2;
            float b0 = bias[col0 + col], b1 = bias[col0 + col + 1];
            int r0 = m0 + wm + i * 16 + g;
            if (MODE == 0) {
                __half2 v0 = __floats2half2_rn(fmaxf(acc[i][j][0] + b0, 0.f),
                                               fmaxf(acc[i][j][1] + b1, 0.f));
                __half2 v1 = __floats2half2_rn(fmaxf(acc[i][j][2] + b0, 0.f),
                                               fmaxf(acc[i][j][3] + b1, 0.f));
                *(__half2*)&g_Hh[(size_t)r0 * HDIM + col0 + col] = v0;
                *(__half2*)&g_Hh[(size_t)(r0 + 8) * HDIM + col0 + col] = v1;
            } else if (MODE == 1) {
                size_t base0 = (size_t)r0 * DD + col0 + col;
                size_t base1 = (size_t)(r0 + 8) * DD + col0 + col;
                g_local[base0 + 0] = acc[i][j][0] + b0;
                g_local[base0 + 1] = acc[i][j][1] + b1;
                g_local[base1 + 0] = acc[i][j][2] + b0;
                g_local[base1 + 1] = acc[i][j][3] + b1;
            } else {
                int b0i = r0 >> 13, n0i = r0 & (NN - 1);
                int b1i = (r0 + 8) >> 13, n1i = (r0 + 8) & (NN - 1);
                int kc = col0 + col;
                g_E[((size_t)b0i * 65 + kc + 0) * NN + n0i] = expf(acc[i][j][0] + b0);
                g_E[((size_t)b0i * 65 + kc + 1) * NN + n0i] = expf(acc[i][j][1] + b1);
                g_E[((size_t)b1i * 65 + kc + 0) * NN + n1i] = expf(acc[i][j][2] + b0);
                g_E[((size_t)b1i * 65 + kc + 1) * NN + n1i] = expf(acc[i][j][3] + b1);
            }
        }
    }
}

// ---------------- dust row of E ----------------
__global__ void k_dustE(const float* __restrict__ dust) {
    int i = blockIdx.x * 256 + threadIdx.x;   // 65536
    int b = i >> 13, n = i & (NN - 1);
    g_E[((size_t)b * 65 + 64) * NN + n] = expf(dust[0]);
}

// ---------------- linear-domain Sinkhorn ----------------
__global__ void k_row() {                      // grid (65, 8), 256 thr
    int m = blockIdx.x, b = blockIdx.y, tid = threadIdx.x;
    const float* row = &g_E[((size_t)b * 65 + m) * NN];
    const float* ev = &g_ev[b * NN];
    float s = 0.f;
    for (int n = tid; n < NN; n += 256) s = fmaf(row[n], ev[n], s);
    __shared__ float red[256];
    red[tid] = s;
    __syncthreads();
    #pragma unroll
    for (int o = 128; o > 0; o >>= 1) {
        if (tid < o) red[tid] += red[tid + o];
        __syncthreads();
    }
    if (tid == 0) {
        float a = (m == 64) ? (8128.f / 8256.f) : (1.f / 8256.f);
        g_eu[b * 65 + m] = a / red[0];
    }
}

__global__ void k_col() {                      // grid (32, 8), 256 thr
    int b = blockIdx.y;
    int n = blockIdx.x * 256 + threadIdx.x;
    __shared__ float us[65];
    if (threadIdx.x < 65) us[threadIdx.x] = g_eu[b * 65 + threadIdx.x];
    __syncthreads();
    const float* col = &g_E[(size_t)b * 65 * NN + n];
    float s = 0.f;
    #pragma unroll
    for (int m = 0; m < 65; m++) s = fmaf(col[(size_t)m * NN], us[m], s);
    g_ev[b * NN + n] = (1.f / 8256.f) / s;
}

// ---------------- aggregation: agg[b,d,k] = sum_n local[b,n,d]*P[b,k,n] ----------------
// P folded on the fly: P = E * eu[k] * ev[n] * 8256
__global__ __launch_bounds__(256) void k_aggp() {
    int b = blockIdx.y, chunk = blockIdx.x;
    int n0 = chunk * 256;
    int tid = threadIdx.x;
    int tx = tid & 15, ty = tid >> 4;
    int k0 = tx * 4, d0 = ty * 8;
    __shared__ float Ls[32][132];
    __shared__ float Ps[32][68];
    float acc[8][4];
    #pragma unroll
    for (int i = 0; i < 8; i++)
        #pragma unroll
        for (int j = 0; j < 4; j++) acc[i][j] = 0.f;

    for (int c = 0; c < 8; c++) {
        #pragma unroll
        for (int t = 0; t < 4; t++) {
            int f = tid + t * 256;
            int nn = f >> 5; int dq = (f & 31) * 4;
            float4 a = *reinterpret_cast<const float4*>(
                &g_local[((size_t)b * NN + n0 + c * 32 + nn) * DD + dq]);
            Ls[nn][dq + 0] = a.x; Ls[nn][dq + 1] = a.y; Ls[nn][dq + 2] = a.z; Ls[nn][dq + 3] = a.w;
        }
        #pragma unroll
        for (int t = 0; t < 2; t++) {
            int f = tid + t * 256;
            int kk = f >> 3; int nq = (f & 7) * 4;
            int nb = n0 + c * 32 + nq;
            float euk = g_eu[b * 65 + kk] * 8256.f;
            float4 e4 = *reinterpret_cast<const float4*>(&g_E[((size_t)b * 65 + kk) * NN + nb]);
            float4 v4 = *reinterpret_cast<const float4*>(&g_ev[b * NN + nb]);
            Ps[nq + 0][kk] = e4.x * v4.x * euk;
            Ps[nq + 1][kk] = e4.y * v4.y * euk;
            Ps[nq + 2][kk] = e4.z * v4.z * euk;
            Ps[nq + 3][kk] = e4.w * v4.w * euk;
        }
        __syncthreads();
        #pragma unroll
        for (int nn = 0; nn < 32; nn++) {
            float a[8], p[4];
            #pragma unroll
            for (int i = 0; i < 8; i++) a[i] = Ls[nn][d0 + i];
            #pragma unroll
            for (int j = 0; j < 4; j++) p[j] = Ps[nn][k0 + j];
            #pragma unroll
            for (int i = 0; i < 8; i++)
                #pragma unroll
                for (int j = 0; j < 4; j++) acc[i][j] = fmaf(a[i], p[j], acc[i][j]);
        }
        __syncthreads();
    }
    float* out = &g_aggp[((size_t)(b * 32 + chunk)) * DD * KK];
    #pragma unroll
    for (int i = 0; i < 8; i++)
        #pragma unroll
        for (int j = 0; j < 4; j++)
            out[(d0 + i) * KK + k0 + j] = acc[i][j];
}

__global__ void k_aggred() {
    int i = blockIdx.x * 256 + threadIdx.x;
    int b = i >> 13, r = i & 8191;
    float s = 0.f;
    #pragma unroll
    for (int c = 0; c < 32; c++) s += g_aggp[((size_t)(b * 32 + c)) * DD * KK + r];
    g_agg[i] = s;
}

// ---------------- final normalization ----------------
__global__ void k_final(float* __restrict__ out) {
    int b = blockIdx.x, tid = threadIdx.x;
    __shared__ float red[256];
    float gtv = g_gt[b * TOKN + tid];
    red[tid] = gtv * gtv;
    __syncthreads();
    for (int s = 128; s > 0; s >>= 1) { if (tid < s) red[tid] += red[tid + s]; __syncthreads(); }
    float S1 = red[0];
    __syncthreads();
    float s2 = 0.f;
    for (int i = tid; i < DD * KK; i += 256) { float v = g_agg[b * DD * KK + i]; s2 += v * v; }
    red[tid] = s2;
    __syncthreads();
    for (int s = 128; s > 0; s >>= 1) { if (tid < s) red[tid] += red[tid + s]; __syncthreads(); }
    float S2 = red[0];
    float n1 = fmaxf(sqrtf(S1), 1e-12f);
    float n2 = fmaxf(sqrtf(S2), 1e-12f);
    float tot = fmaxf(sqrtf(S1 / (n1 * n1) + S2 / (n2 * n2)), 1e-12f);
    out[(size_t)b * OUTW + tid] = (gtv / n1) / tot;
    for (int i = tid; i < DD * KK; i += 256)
        out[(size_t)b * OUTW + TOKN + i] = (g_agg[b * DD * KK + i] / n2) / tot;
}

// ---------------- launcher ----------------
extern "C" void kernel_launch(void* const* d_in, const int* in_sizes, int n_in,
                              void* d_out, int out_size) {
    const float* x     = (const float*)d_in[0];
    const float* gem_w = (const float*)d_in[1];
    const float* dust  = (const float*)d_in[2];
    const float* tW1 = (const float*)d_in[3];  const float* tb1 = (const float*)d_in[4];
    const float* tW2 = (const float*)d_in[5];  const float* tb2 = (const float*)d_in[6];
    const float* cW1 = (const float*)d_in[7];  const float* cb1 = (const float*)d_in[8];
    const float* cW2 = (const float*)d_in[9];  const float* cb2 = (const float*)d_in[10];
    const float* sW1 = (const float*)d_in[11]; const float* sb1 = (const float*)d_in[12];
    const float* sW2 = (const float*)d_in[13]; const float* sb2 = (const float*)d_in[14];
    float* out = (float*)d_out;

    const int SM1 = 4 * (128 + 128) * 40 * 2;   // 81920 B (BN=128)
    const int SM2 = 4 * (128 + 64) * 40 * 2;    // 61440 B (BN=64)
    cudaFuncSetAttribute(k_mm<128, 0>, cudaFuncAttributeMaxDynamicSharedMemorySize, SM1);
    cudaFuncSetAttribute(k_mm<128, 1>, cudaFuncAttributeMaxDynamicSharedMemorySize, SM1);
    cudaFuncSetAttribute(k_mm<64, 2>,  cudaFuncAttributeMaxDynamicSharedMemorySize, SM2);

    k_prep<<<2432, 256>>>(cW1, cb1, sW1, sb1, cW2, cb2, sW2, sb2);
    k_initev<<<256, 256>>>();
    k_gem_part<<<dim3(32, 8), 512>>>(x, gem_w);   // also writes g_Xh
    k_gem_fin<<<8, 512>>>(gem_w);
    k_tok1<<<512, 256>>>(tW1, tb1);
    k_tok2<<<256, 256>>>(tW2, tb2);

    k_mm<128, 0><<<dim3(8, 512), 256, SM1>>>();   // Hh = relu(Xh @ W1h^T + b1)
    k_mm<128, 1><<<dim3(1, 512), 256, SM1>>>();   // local
    k_mm<64, 2><<<dim3(1, 512), 256, SM2>>>();    // E = exp(scores)
    k_dustE<<<256, 256>>>(dust);

    for (int it = 0; it < 3; it++) {
        k_row<<<dim3(65, 8), 256>>>();
        k_col<<<dim3(32, 8), 256>>>();
    }

    k_aggp<<<dim3(32, 8), 256>>>();
    k_aggred<<<256, 256>>>();
    k_final<<<8, 256>>>(out);
}